// round 2
// baseline (speedup 1.0000x reference)
#include <cuda_runtime.h>
#include <math.h>

// ---------------------------------------------------------------------------
// Problem constants
// ---------------------------------------------------------------------------
#define NVOX   131072          // B*S^3 = 4*32768
#define CIN    256
#define NH     16
#define DK     32
#define DV     16
#define QK     512             // NH*DK
#define VD     256             // NH*DV
#define CAT    1536            // 512 q + 512 k + 256 v + 256 res
#define FF     1024            // 2*NH*DK

// ---------------------------------------------------------------------------
// Device scratch (static __device__ arrays: allocation-free per harness rules)
// ---------------------------------------------------------------------------
__device__ float g_Wcat[CIN * CAT];                 // concatenated [256,1536]
__device__ float g_bcat[CAT];
__device__ float g_bnscale[VD];
__device__ float g_bnbias[VD];
__device__ float g_qkvc[(size_t)NVOX * CAT];        // q|k|v|res per voxel
__device__ float g_attn[(size_t)NVOX * VD];         // attention output
__device__ float g_inter[(size_t)NVOX * FF];        // FFN hidden

// ---------------------------------------------------------------------------
// Pack kernel: build Wcat/bcat, fold BN params
// ---------------------------------------------------------------------------
__global__ void pack_kernel(const float* __restrict__ Wq, const float* __restrict__ bq,
                            const float* __restrict__ Wk, const float* __restrict__ bk,
                            const float* __restrict__ Wv, const float* __restrict__ bv,
                            const float* __restrict__ Wc, const float* __restrict__ bc,
                            const float* __restrict__ gamma, const float* __restrict__ beta,
                            const float* __restrict__ mu, const float* __restrict__ var)
{
    int idx = blockIdx.x * blockDim.x + threadIdx.x;
    int stride = gridDim.x * blockDim.x;
    for (int i = idx; i < CIN * CAT; i += stride) {
        int r = i / CAT, c = i % CAT;
        float w;
        if (c < 512)       w = Wq[r * 512 + c];
        else if (c < 1024) w = Wk[r * 512 + (c - 512)];
        else if (c < 1280) w = Wv[r * 256 + (c - 1024)];
        else               w = Wc[r * 256 + (c - 1280)];
        g_Wcat[i] = w;
    }
    if (idx < CAT) {
        int c = idx; float b;
        if (c < 512)       b = bq[c];
        else if (c < 1024) b = bk[c - 512];
        else if (c < 1280) b = bv[c - 1024];
        else               b = bc[c - 1280];
        g_bcat[c] = b;
    }
    if (idx < VD) {
        float s = gamma[idx] * rsqrtf(var[idx] + 1e-6f);
        g_bnscale[idx] = s;
        g_bnbias[idx]  = beta[idx] - mu[idx] * s;
    }
}

// ---------------------------------------------------------------------------
// Tiled SGEMM: C[M,N] = A[M,K] @ B[K,N] + bias, with fused epilogues.
//   MODE 0: relu only on cols >= 1280  (qkvc projection)
//   MODE 1: relu everywhere           (FFN hidden)
//   MODE 2: y = (res + acc+bias)*bnscale + bnbias  (final output)
// BM=BN=128, BK=16, 256 threads, 8x8 per-thread microtile.
// All problem dims divide the tiles exactly (M=131072, N in {1536,1024,256},
// K in {256,1024}).
// ---------------------------------------------------------------------------
#define BM 128
#define BN 128
#define BKK 16
#define TM 8
#define TN 8

template<int MODE>
__global__ __launch_bounds__(256)
void sgemm_kernel(const float* __restrict__ A, const float* __restrict__ B,
                  float* __restrict__ C, int M, int Nn, int K,
                  const float* __restrict__ bias,
                  const float* __restrict__ res)
{
    __shared__ float As[BKK][BM + 4];   // transposed, padded against conflicts
    __shared__ float Bs[BKK][BN];

    const int row0 = blockIdx.y * BM;
    const int col0 = blockIdx.x * BN;
    const int tid  = threadIdx.x;

    // A-tile loads: 128x16 floats = 512 float4, 2 per thread
    const int a_row = tid >> 2;            // 0..63 (+64)
    const int a_col = (tid & 3) * 4;       // 0,4,8,12
    // B-tile loads: 16x128 floats = 512 float4, 2 per thread
    const int b_row = tid >> 5;            // 0..7 (+8)
    const int b_col = (tid & 31) * 4;

    const int ty = tid / 16, tx = tid % 16;
    const int trow = ty * TM;              // 0..120
    const int tcol = tx * TN;

    float acc[TM][TN];
    #pragma unroll
    for (int i = 0; i < TM; i++)
        #pragma unroll
        for (int j = 0; j < TN; j++) acc[i][j] = 0.0f;

    for (int k0 = 0; k0 < K; k0 += BKK) {
        #pragma unroll
        for (int i = 0; i < 2; i++) {
            int r = a_row + i * 64;
            float4 av = *reinterpret_cast<const float4*>(
                &A[(size_t)(row0 + r) * K + k0 + a_col]);
            As[a_col + 0][r] = av.x;
            As[a_col + 1][r] = av.y;
            As[a_col + 2][r] = av.z;
            As[a_col + 3][r] = av.w;
        }
        #pragma unroll
        for (int i = 0; i < 2; i++) {
            int r = b_row + i * 8;
            *reinterpret_cast<float4*>(&Bs[r][b_col]) =
                *reinterpret_cast<const float4*>(
                    &B[(size_t)(k0 + r) * Nn + col0 + b_col]);
        }
        __syncthreads();

        #pragma unroll
        for (int kk = 0; kk < BKK; kk++) {
            float a_frag[TM], b_frag[TN];
            float4 a0 = *reinterpret_cast<const float4*>(&As[kk][trow]);
            float4 a1 = *reinterpret_cast<const float4*>(&As[kk][trow + 4]);
            a_frag[0]=a0.x; a_frag[1]=a0.y; a_frag[2]=a0.z; a_frag[3]=a0.w;
            a_frag[4]=a1.x; a_frag[5]=a1.y; a_frag[6]=a1.z; a_frag[7]=a1.w;
            float4 b0 = *reinterpret_cast<const float4*>(&Bs[kk][tcol]);
            float4 b1 = *reinterpret_cast<const float4*>(&Bs[kk][tcol + 4]);
            b_frag[0]=b0.x; b_frag[1]=b0.y; b_frag[2]=b0.z; b_frag[3]=b0.w;
            b_frag[4]=b1.x; b_frag[5]=b1.y; b_frag[6]=b1.z; b_frag[7]=b1.w;
            #pragma unroll
            for (int i = 0; i < TM; i++)
                #pragma unroll
                for (int j = 0; j < TN; j++)
                    acc[i][j] += a_frag[i] * b_frag[j];
        }
        __syncthreads();
    }

    #pragma unroll
    for (int i = 0; i < TM; i++) {
        int r = row0 + trow + i;
        #pragma unroll
        for (int j = 0; j < TN; j++) {
            int c = col0 + tcol + j;
            float v = acc[i][j] + bias[c];
            if (MODE == 0) { if (c >= 1280) v = fmaxf(v, 0.0f); }
            if (MODE == 1) { v = fmaxf(v, 0.0f); }
            if (MODE == 2) {
                float rr = res[(size_t)r * CAT + 1280 + c];
                v = (rr + v) * g_bnscale[c] + g_bnbias[c];
            }
            C[(size_t)r * Nn + c] = v;
        }
    }
}

// ---------------------------------------------------------------------------
// Per-voxel head attention: 1 block (256 threads) per voxel.
// scores[h][g] = q_h . k_g / sqrt(DK); softmax over g; out = P @ V
// ---------------------------------------------------------------------------
__global__ __launch_bounds__(256)
void attn_kernel(const float* __restrict__ qkvc, float* __restrict__ out)
{
    __shared__ float qs[QK];
    __shared__ float ks[QK];
    __shared__ float vs[VD];
    __shared__ float prob[NH][NH + 1];

    const size_t vox = blockIdx.x;
    const float* base = qkvc + vox * CAT;
    const int t = threadIdx.x;

    for (int i = t; i < QK; i += 256) {
        qs[i] = base[i];
        ks[i] = base[512 + i];
    }
    vs[t] = base[1024 + t];
    __syncthreads();

    const int h = t >> 4;      // 0..15
    const int g = t & 15;      // 0..15

    // score (h,g)
    float s = 0.0f;
    const float* qh = &qs[h * DK];
    const float* kg = &ks[g * DK];
    #pragma unroll
    for (int d = 0; d < DK; d++) s += qh[d] * kg[d];
    prob[h][g] = s * 0.17677669529663687f;   // 1/sqrt(32)
    __syncthreads();

    // softmax along g (one thread per row; cheap at 16 elems)
    if (g == 0) {
        float mx = prob[h][0];
        #pragma unroll
        for (int j = 1; j < NH; j++) mx = fmaxf(mx, prob[h][j]);
        float sum = 0.0f;
        float e[NH];
        #pragma unroll
        for (int j = 0; j < NH; j++) { e[j] = __expf(prob[h][j] - mx); sum += e[j]; }
        float inv = 1.0f / sum;
        #pragma unroll
        for (int j = 0; j < NH; j++) prob[h][j] = e[j] * inv;
    }
    __syncthreads();

    // attn_out[h][dv], dv = g
    float o = 0.0f;
    #pragma unroll
    for (int j = 0; j < NH; j++) o += prob[h][j] * vs[j * DV + g];
    out[vox * VD + h * DV + g] = o;
}

// ---------------------------------------------------------------------------
// Launch
// ---------------------------------------------------------------------------
extern "C" void kernel_launch(void* const* d_in, const int* in_sizes, int n_in,
                              void* d_out, int out_size)
{
    const float* x     = (const float*)d_in[0];
    const float* Wq    = (const float*)d_in[1];
    const float* bq    = (const float*)d_in[2];
    const float* Wk    = (const float*)d_in[3];
    const float* bk    = (const float*)d_in[4];
    const float* Wv    = (const float*)d_in[5];
    const float* bv    = (const float*)d_in[6];
    const float* W1    = (const float*)d_in[7];
    const float* b1    = (const float*)d_in[8];
    const float* Wo    = (const float*)d_in[9];
    const float* bo    = (const float*)d_in[10];
    const float* Wc    = (const float*)d_in[11];
    const float* bc    = (const float*)d_in[12];
    const float* gamma = (const float*)d_in[13];
    const float* beta  = (const float*)d_in[14];
    const float* mu    = (const float*)d_in[15];
    const float* var   = (const float*)d_in[16];
    float* out = (float*)d_out;

    void* p;
    cudaGetSymbolAddress(&p, g_Wcat);  float* Wcat  = (float*)p;
    cudaGetSymbolAddress(&p, g_bcat);  float* bcat  = (float*)p;
    cudaGetSymbolAddress(&p, g_qkvc);  float* qkvc  = (float*)p;
    cudaGetSymbolAddress(&p, g_attn);  float* attn  = (float*)p;
    cudaGetSymbolAddress(&p, g_inter); float* inter = (float*)p;

    pack_kernel<<<512, 256>>>(Wq, bq, Wk, bk, Wv, bv, Wc, bc, gamma, beta, mu, var);

    // qkvc = X @ Wcat + bcat (relu on res cols)
    {
        dim3 grid(CAT / BN, NVOX / BM);
        sgemm_kernel<0><<<grid, 256>>>(x, Wcat, qkvc, NVOX, CAT, CIN, bcat, nullptr);
    }

    // per-voxel attention
    attn_kernel<<<NVOX, 256>>>(qkvc, attn);

    // inter = relu(attn @ W1 + b1)
    {
        dim3 grid(FF / BN, NVOX / BM);
        sgemm_kernel<1><<<grid, 256>>>(attn, W1, inter, NVOX, FF, VD, b1, nullptr);
    }

    // out = (res + inter @ Wo + bo) * bnscale + bnbias
    {
        dim3 grid(VD / BN, NVOX / BM);
        sgemm_kernel<2><<<grid, 256>>>(inter, Wo, out, NVOX, VD, FF, bo, qkvc);
    }
}

// round 4
// speedup vs baseline: 1.9823x; 1.9823x over previous
#include <cuda_runtime.h>
#include <cstdint>
#include <math.h>

// ---------------------------------------------------------------------------
// Problem constants
// ---------------------------------------------------------------------------
#define NVOX   131072
#define CIN    256
#define NH     16
#define DK     32
#define DV     16
#define QK     512
#define VD     256
#define CAT    1536          // q(512) | k(512) | v(256) | res(256)
#define FF     1024

// ---------------------------------------------------------------------------
// Device scratch
// ---------------------------------------------------------------------------
__device__ float g_Wcat[CIN * CAT];      // [256,1536] tf32-rounded, row-major [K,N]
__device__ float g_W1r[VD * FF];         // [256,1024]
__device__ float g_Wor[FF * VD];         // [1024,256]
__device__ float g_bcat[CAT];
__device__ float g_bnscale[VD];
__device__ float g_bnbias[VD];
__device__ float g_qkvc[(size_t)NVOX * CAT];
__device__ float g_attn[(size_t)NVOX * VD];
__device__ float g_inter[(size_t)NVOX * FF];

__device__ __forceinline__ float to_tf32(float x) {
    float r; asm("cvt.rna.tf32.f32 %0, %1;" : "=f"(r) : "f"(x)); return r;
}

__device__ __forceinline__ void mma1688(float* d, const uint32_t* a, const uint32_t* b) {
    asm volatile(
        "mma.sync.aligned.m16n8k8.row.col.f32.tf32.tf32.f32 "
        "{%0,%1,%2,%3}, {%4,%5,%6,%7}, {%8,%9}, {%0,%1,%2,%3};"
        : "+f"(d[0]), "+f"(d[1]), "+f"(d[2]), "+f"(d[3])
        : "r"(a[0]), "r"(a[1]), "r"(a[2]), "r"(a[3]),
          "r"(b[0]), "r"(b[1]));
}

// ---------------------------------------------------------------------------
// Pack: round weights to tf32 (keep [K,N] layout), concat, fold BN
// ---------------------------------------------------------------------------
__global__ void pack_kernel(const float* __restrict__ Wq, const float* __restrict__ bq,
                            const float* __restrict__ Wk, const float* __restrict__ bk,
                            const float* __restrict__ Wv, const float* __restrict__ bv,
                            const float* __restrict__ W1,
                            const float* __restrict__ Wo,
                            const float* __restrict__ Wc, const float* __restrict__ bc,
                            const float* __restrict__ gamma, const float* __restrict__ beta,
                            const float* __restrict__ mu, const float* __restrict__ var)
{
    int idx = blockIdx.x * blockDim.x + threadIdx.x;
    int st = gridDim.x * blockDim.x;
    for (int i = idx; i < CIN * CAT; i += st) {
        int k = i / CAT, n = i % CAT;
        float w;
        if (n < 512)       w = Wq[k * 512 + n];
        else if (n < 1024) w = Wk[k * 512 + (n - 512)];
        else if (n < 1280) w = Wv[k * 256 + (n - 1024)];
        else               w = Wc[k * 256 + (n - 1280)];
        g_Wcat[i] = to_tf32(w);
    }
    for (int i = idx; i < VD * FF; i += st) g_W1r[i] = to_tf32(W1[i]);
    for (int i = idx; i < FF * VD; i += st) g_Wor[i] = to_tf32(Wo[i]);
    for (int i = idx; i < CAT; i += st) {
        float b;
        if (i < 512)       b = bq[i];
        else if (i < 1024) b = bk[i - 512];
        else if (i < 1280) b = bv[i - 1024];
        else               b = bc[i - 1280];
        g_bcat[i] = b;
    }
    for (int i = idx; i < VD; i += st) {
        float s = gamma[i] * rsqrtf(var[i] + 1e-6f);
        g_bnscale[i] = s;
        g_bnbias[i]  = beta[i] - mu[i] * s;
    }
}

// ---------------------------------------------------------------------------
// TF32 mma.sync GEMM: C[M,Nn] = A[M,K] @ B[K,Nn] (+ fused epilogue MODE)
//   MODE 0: relu on cols >= 1280 only       (qkvc projection)
//   MODE 1: relu + tf32-round               (FFN hidden)
//   MODE 2: (res + acc+bias)*bns + bnb      (final)
// BM=BN=128, BK=32, 256 threads = 8 warps (2x4), warp tile 64x32.
// ---------------------------------------------------------------------------
#define BM 128
#define BN 128
#define BK 32
#define ASTR 36      // A smem row stride (floats): [128][36]
#define BSTR 136     // B smem row stride (floats): [32][136]
#define ABYTES (BM * ASTR)            // floats
#define BBYTES (BK * BSTR)            // floats
#define BUF (ABYTES + BBYTES)         // 8960 floats per stage

template<int MODE>
__global__ __launch_bounds__(256)
void gemm_mma(const float* __restrict__ A, const float* __restrict__ B,
              float* __restrict__ C, int Nn, int K,
              const float* __restrict__ bias,
              const float* __restrict__ resp)
{
    extern __shared__ float sm[];

    const int tid  = threadIdx.x;
    const int wid  = tid >> 5;
    const int lane = tid & 31;
    const int wr = wid >> 2;           // 0..1
    const int wc = wid & 3;            // 0..3
    const int group = lane >> 2;       // 0..7
    const int tig = lane & 3;          // 0..3

    const int row0 = blockIdx.y * BM;
    const int col0 = blockIdx.x * BN;
    const int KT = K / BK;

    float acc[4][4][4];
    #pragma unroll
    for (int mi = 0; mi < 4; mi++)
        #pragma unroll
        for (int ni = 0; ni < 4; ni++)
            #pragma unroll
            for (int r = 0; r < 4; r++) acc[mi][ni][r] = 0.0f;

    float4 ra[4], rb[4];

    // ---- global loads for k-tile (register staged) ----
    auto ldg = [&](int k0) {
        #pragma unroll
        for (int i = 0; i < 4; i++) {
            int f = tid + 256 * i;
            int r = f >> 3, c4 = f & 7;          // A: row, float4-col
            ra[i] = *reinterpret_cast<const float4*>(
                &A[(size_t)(row0 + r) * K + k0 + c4 * 4]);
            int kB = f >> 5, n4 = f & 31;        // B: k-row, float4-col
            rb[i] = *reinterpret_cast<const float4*>(
                &B[(size_t)(k0 + kB) * Nn + col0 + n4 * 4]);
        }
    };
    auto sts = [&](float* buf) {
        float* As = buf;
        float* Bs = buf + ABYTES;
        #pragma unroll
        for (int i = 0; i < 4; i++) {
            int f = tid + 256 * i;
            int r = f >> 3, c4 = f & 7;
            float4 v = ra[i];
            v.x = to_tf32(v.x); v.y = to_tf32(v.y);
            v.z = to_tf32(v.z); v.w = to_tf32(v.w);
            *reinterpret_cast<float4*>(&As[r * ASTR + c4 * 4]) = v;
            int kB = f >> 5, n4 = f & 31;
            *reinterpret_cast<float4*>(&Bs[kB * BSTR + n4 * 4]) = rb[i];
        }
    };
    auto compute = [&](const float* buf) {
        const float* As = buf;
        const float* Bs = buf + ABYTES;
        #pragma unroll
        for (int ks = 0; ks < 4; ks++) {
            const int kk = ks * 8 + tig;
            uint32_t af[4][4], bf[4][2];
            #pragma unroll
            for (int mi = 0; mi < 4; mi++) {
                int r = wr * 64 + mi * 16 + group;
                af[mi][0] = __float_as_uint(As[r * ASTR + kk]);
                af[mi][1] = __float_as_uint(As[(r + 8) * ASTR + kk]);
                af[mi][2] = __float_as_uint(As[r * ASTR + kk + 4]);
                af[mi][3] = __float_as_uint(As[(r + 8) * ASTR + kk + 4]);
            }
            #pragma unroll
            for (int ni = 0; ni < 4; ni++) {
                int c = wc * 32 + ni * 8 + group;
                bf[ni][0] = __float_as_uint(Bs[kk * BSTR + c]);
                bf[ni][1] = __float_as_uint(Bs[(kk + 4) * BSTR + c]);
            }
            #pragma unroll
            for (int mi = 0; mi < 4; mi++)
                #pragma unroll
                for (int ni = 0; ni < 4; ni++)
                    mma1688(acc[mi][ni], af[mi], bf[ni]);
        }
    };

    // ---- pipelined main loop (double-buffered smem) ----
    ldg(0);
    sts(sm);
    __syncthreads();
    for (int kt = 0; kt < KT; kt++) {
        if (kt + 1 < KT) ldg((kt + 1) * BK);
        compute(sm + (kt & 1) * BUF);
        if (kt + 1 < KT) {
            sts(sm + ((kt + 1) & 1) * BUF);
            __syncthreads();
        }
    }

    // ---- epilogue ----
    #pragma unroll
    for (int mi = 0; mi < 4; mi++) {
        #pragma unroll
        for (int ni = 0; ni < 4; ni++) {
            const int cg = col0 + wc * 32 + ni * 8 + tig * 2;
            #pragma unroll
            for (int half = 0; half < 2; half++) {
                const size_t r = (size_t)row0 + wr * 64 + mi * 16 + group + half * 8;
                float2 v;
                #pragma unroll
                for (int q = 0; q < 2; q++) {
                    int c = cg + q;
                    float x = acc[mi][ni][half * 2 + q] + __ldg(&bias[c]);
                    if (MODE == 0) { if (c >= 1280) x = fmaxf(x, 0.0f); }
                    if (MODE == 1) { x = to_tf32(fmaxf(x, 0.0f)); }
                    if (MODE == 2) {
                        float rr = __ldg(&resp[r * CAT + 1280 + c]);
                        x = (rr + x) * g_bnscale[c] + g_bnbias[c];
                    }
                    (&v.x)[q] = x;
                }
                *reinterpret_cast<float2*>(&C[r * Nn + cg]) = v;
            }
        }
    }
}

// ---------------------------------------------------------------------------
// Per-voxel head attention: 1 block (256 threads) per voxel
// ---------------------------------------------------------------------------
__global__ __launch_bounds__(256)
void attn_kernel(const float* __restrict__ qkvc, float* __restrict__ out)
{
    __shared__ float qs[QK];
    __shared__ float ks[QK];
    __shared__ float vs[VD];
    __shared__ float prob[NH][NH + 1];

    const size_t vox = blockIdx.x;
    const float* base = qkvc + vox * CAT;
    const int t = threadIdx.x;

    for (int i = t; i < QK; i += 256) {
        qs[i] = base[i];
        ks[i] = base[512 + i];
    }
    vs[t] = base[1024 + t];
    __syncthreads();

    const int h = t >> 4;
    const int g = t & 15;

    float s = 0.0f;
    const float* qh = &qs[h * DK];
    const float* kg = &ks[g * DK];
    #pragma unroll
    for (int d = 0; d < DK; d++) s += qh[d] * kg[d];
    prob[h][g] = s * 0.17677669529663687f;
    __syncthreads();

    if (g == 0) {
        float mx = prob[h][0];
        #pragma unroll
        for (int j = 1; j < NH; j++) mx = fmaxf(mx, prob[h][j]);
        float sum = 0.0f;
        float e[NH];
        #pragma unroll
        for (int j = 0; j < NH; j++) { e[j] = __expf(prob[h][j] - mx); sum += e[j]; }
        float inv = 1.0f / sum;
        #pragma unroll
        for (int j = 0; j < NH; j++) prob[h][j] = e[j] * inv;
    }
    __syncthreads();

    float o = 0.0f;
    #pragma unroll
    for (int j = 0; j < NH; j++) o += prob[h][j] * vs[j * DV + g];
    out[vox * VD + h * DV + g] = o;
}

// ---------------------------------------------------------------------------
// Launch
// ---------------------------------------------------------------------------
extern "C" void kernel_launch(void* const* d_in, const int* in_sizes, int n_in,
                              void* d_out, int out_size)
{
    const float* x     = (const float*)d_in[0];
    const float* Wq    = (const float*)d_in[1];
    const float* bq    = (const float*)d_in[2];
    const float* Wk    = (const float*)d_in[3];
    const float* bk    = (const float*)d_in[4];
    const float* Wv    = (const float*)d_in[5];
    const float* bv    = (const float*)d_in[6];
    const float* W1    = (const float*)d_in[7];
    const float* b1    = (const float*)d_in[8];
    const float* Wo    = (const float*)d_in[9];
    const float* bo    = (const float*)d_in[10];
    const float* Wc    = (const float*)d_in[11];
    const float* bc    = (const float*)d_in[12];
    const float* gamma = (const float*)d_in[13];
    const float* beta  = (const float*)d_in[14];
    const float* mu    = (const float*)d_in[15];
    const float* var   = (const float*)d_in[16];
    float* out = (float*)d_out;

    void* p;
    cudaGetSymbolAddress(&p, g_Wcat);  float* Wcat = (float*)p;
    cudaGetSymbolAddress(&p, g_W1r);   float* W1r  = (float*)p;
    cudaGetSymbolAddress(&p, g_Wor);   float* Wor  = (float*)p;
    cudaGetSymbolAddress(&p, g_bcat);  float* bcat = (float*)p;
    cudaGetSymbolAddress(&p, g_qkvc);  float* qkvc = (float*)p;
    cudaGetSymbolAddress(&p, g_attn);  float* attn = (float*)p;
    cudaGetSymbolAddress(&p, g_inter); float* inter = (float*)p;

    const int SMEM = 2 * BUF * 4;   // 71680 bytes
    cudaFuncSetAttribute(gemm_mma<0>, cudaFuncAttributeMaxDynamicSharedMemorySize, SMEM);
    cudaFuncSetAttribute(gemm_mma<1>, cudaFuncAttributeMaxDynamicSharedMemorySize, SMEM);
    cudaFuncSetAttribute(gemm_mma<2>, cudaFuncAttributeMaxDynamicSharedMemorySize, SMEM);

    pack_kernel<<<512, 256>>>(Wq, bq, Wk, bk, Wv, bv, W1, Wo, Wc, bc,
                              gamma, beta, mu, var);

    // qkvc = x @ Wcat + bcat (relu on res cols)
    {
        dim3 grid(CAT / BN, NVOX / BM);
        gemm_mma<0><<<grid, 256, SMEM>>>(x, Wcat, qkvc, CAT, CIN, bcat, nullptr);
    }

    attn_kernel<<<NVOX, 256>>>(qkvc, attn);

    // inter = relu(attn @ W1 + b1), tf32-rounded
    {
        dim3 grid(FF / BN, NVOX / BM);
        gemm_mma<1><<<grid, 256, SMEM>>>(attn, W1r, inter, FF, VD, b1, nullptr);
    }

    // out = (res + inter @ Wo + bo) * bnscale + bnbias
    {
        dim3 grid(VD / BN, NVOX / BM);
        gemm_mma<2><<<grid, 256, SMEM>>>(inter, Wor, out, VD, FF, bo, qkvc);
    }
}

// round 5
// speedup vs baseline: 2.5482x; 1.2855x over previous
#include <cuda_runtime.h>
#include <cstdint>
#include <math.h>

// ---------------------------------------------------------------------------
// Problem constants
// ---------------------------------------------------------------------------
#define NVOX   131072
#define CIN    256
#define NH     16
#define DK     32
#define DV     16
#define QK     512
#define VD     256
#define CAT    1536          // q(512) | k(512) | v(256) | res(256)
#define FF     1024

// ---------------------------------------------------------------------------
// Device scratch
// ---------------------------------------------------------------------------
__device__ float g_Wcat[CIN * CAT];      // [256,1536] tf32-rounded [K,N]
__device__ float g_W1r[VD * FF];
__device__ float g_Wor[FF * VD];
__device__ float g_bcat[CAT];
__device__ float g_bnscale[VD];
__device__ float g_bnbias[VD];
__device__ float g_xr[(size_t)NVOX * CIN];       // tf32-rounded x
__device__ float g_qkvc[(size_t)NVOX * CAT];
__device__ float g_attn[(size_t)NVOX * VD];      // tf32-rounded
__device__ float g_inter[(size_t)NVOX * FF];     // tf32-rounded

__device__ __forceinline__ float to_tf32(float x) {
    float r; asm("cvt.rna.tf32.f32 %0, %1;" : "=f"(r) : "f"(x)); return r;
}
__device__ __forceinline__ uint32_t smem_u32(const void* p) {
    uint32_t a;
    asm("{ .reg .u64 t; cvta.to.shared.u64 t, %1; cvt.u32.u64 %0, t; }"
        : "=r"(a) : "l"(p));
    return a;
}
__device__ __forceinline__ void cp16(uint32_t dst, const void* src) {
    asm volatile("cp.async.cg.shared.global [%0], [%1], 16;"
                 :: "r"(dst), "l"(src) : "memory");
}
__device__ __forceinline__ void cp_commit() {
    asm volatile("cp.async.commit_group;" ::: "memory");
}
template<int N>
__device__ __forceinline__ void cp_wait() {
    asm volatile("cp.async.wait_group %0;" :: "n"(N) : "memory");
}

__device__ __forceinline__ void mma1688(float* d, const uint32_t* a, const uint32_t* b) {
    asm volatile(
        "mma.sync.aligned.m16n8k8.row.col.f32.tf32.tf32.f32 "
        "{%0,%1,%2,%3}, {%4,%5,%6,%7}, {%8,%9}, {%0,%1,%2,%3};"
        : "+f"(d[0]), "+f"(d[1]), "+f"(d[2]), "+f"(d[3])
        : "r"(a[0]), "r"(a[1]), "r"(a[2]), "r"(a[3]),
          "r"(b[0]), "r"(b[1]));
}

// ---------------------------------------------------------------------------
// Pack weights (tf32 RNA), concat biases, fold BN
// ---------------------------------------------------------------------------
__global__ void pack_kernel(const float* __restrict__ Wq, const float* __restrict__ bq,
                            const float* __restrict__ Wk, const float* __restrict__ bk,
                            const float* __restrict__ Wv, const float* __restrict__ bv,
                            const float* __restrict__ W1,
                            const float* __restrict__ Wo,
                            const float* __restrict__ Wc, const float* __restrict__ bc,
                            const float* __restrict__ gamma, const float* __restrict__ beta,
                            const float* __restrict__ mu, const float* __restrict__ var)
{
    int idx = blockIdx.x * blockDim.x + threadIdx.x;
    int st = gridDim.x * blockDim.x;
    for (int i = idx; i < CIN * CAT; i += st) {
        int k = i / CAT, n = i % CAT;
        float w;
        if (n < 512)       w = Wq[k * 512 + n];
        else if (n < 1024) w = Wk[k * 512 + (n - 512)];
        else if (n < 1280) w = Wv[k * 256 + (n - 1024)];
        else               w = Wc[k * 256 + (n - 1280)];
        g_Wcat[i] = to_tf32(w);
    }
    for (int i = idx; i < VD * FF; i += st) g_W1r[i] = to_tf32(W1[i]);
    for (int i = idx; i < FF * VD; i += st) g_Wor[i] = to_tf32(Wo[i]);
    for (int i = idx; i < CAT; i += st) {
        float b;
        if (i < 512)       b = bq[i];
        else if (i < 1024) b = bk[i - 512];
        else if (i < 1280) b = bv[i - 1024];
        else               b = bc[i - 1280];
        g_bcat[i] = b;
    }
    for (int i = idx; i < VD; i += st) {
        float s = gamma[i] * rsqrtf(var[i] + 1e-6f);
        g_bnscale[i] = s;
        g_bnbias[i]  = beta[i] - mu[i] * s;
    }
}

// Pre-round x to tf32 so GEMM1 can stream it raw via cp.async
__global__ void round_x_kernel(const float4* __restrict__ in, float4* __restrict__ out)
{
    const int n4 = NVOX * CIN / 4;
    int idx = blockIdx.x * blockDim.x + threadIdx.x;
    int st = gridDim.x * blockDim.x;
    for (int i = idx; i < n4; i += st) {
        float4 v = in[i];
        v.x = to_tf32(v.x); v.y = to_tf32(v.y);
        v.z = to_tf32(v.z); v.w = to_tf32(v.w);
        out[i] = v;
    }
}

// ---------------------------------------------------------------------------
// TF32 mma.sync GEMM, cp.async 3-stage pipeline.
// BM=BN=128, BK=32, 256 threads = 8 warps (2x4), warp tile 64x32.
//   MODE 0: relu on cols >= 1280 only
//   MODE 1: relu + tf32-round
//   MODE 2: (res + acc+bias)*bns + bnb
// ---------------------------------------------------------------------------
#define BM 128
#define BN 128
#define BK 32
#define ASTR 36          // floats
#define BSTR 136         // floats
#define AFLT (BM * ASTR)             // 4608 floats
#define STAGE_FLT (AFLT + BK * BSTR) // 8960 floats
#define STAGE_BYTES (STAGE_FLT * 4)  // 35840 bytes
#define NSTAGE 3

template<int MODE>
__global__ __launch_bounds__(256, 2)
void gemm_mma(const float* __restrict__ A, const float* __restrict__ B,
              float* __restrict__ C, int Nn, int K,
              const float* __restrict__ bias,
              const float* __restrict__ resp)
{
    extern __shared__ float sm[];

    const int tid  = threadIdx.x;
    const int wid  = tid >> 5;
    const int lane = tid & 31;
    const int wr = wid >> 2;
    const int wc = wid & 3;
    const int group = lane >> 2;
    const int tig = lane & 3;

    const int row0 = blockIdx.y * BM;
    const int col0 = blockIdx.x * BN;
    const int KT = K / BK;

    const uint32_t smemU = smem_u32(sm);

    float acc[4][4][4];
    #pragma unroll
    for (int mi = 0; mi < 4; mi++)
        #pragma unroll
        for (int ni = 0; ni < 4; ni++)
            #pragma unroll
            for (int r = 0; r < 4; r++) acc[mi][ni][r] = 0.0f;

    auto ldgsts = [&](int stage, int k0) {
        const uint32_t aS = smemU + stage * STAGE_BYTES;
        const uint32_t bS = aS + AFLT * 4;
        #pragma unroll
        for (int i = 0; i < 4; i++) {
            int f = tid + 256 * i;
            int r = f >> 3, c4 = f & 7;
            cp16(aS + r * (ASTR * 4) + c4 * 16,
                 &A[(size_t)(row0 + r) * K + k0 + c4 * 4]);
            int kB = f >> 5, n4 = f & 31;
            cp16(bS + kB * (BSTR * 4) + n4 * 16,
                 &B[(size_t)(k0 + kB) * Nn + col0 + n4 * 4]);
        }
        cp_commit();
    };

    auto compute = [&](const float* buf) {
        const float* As = buf;
        const float* Bs = buf + AFLT;
        #pragma unroll
        for (int ks = 0; ks < 4; ks++) {
            const int kk = ks * 8 + tig;
            uint32_t af[4][4], bf[4][2];
            #pragma unroll
            for (int mi = 0; mi < 4; mi++) {
                int r = wr * 64 + mi * 16 + group;
                af[mi][0] = __float_as_uint(As[r * ASTR + kk]);
                af[mi][1] = __float_as_uint(As[(r + 8) * ASTR + kk]);
                af[mi][2] = __float_as_uint(As[r * ASTR + kk + 4]);
                af[mi][3] = __float_as_uint(As[(r + 8) * ASTR + kk + 4]);
            }
            #pragma unroll
            for (int ni = 0; ni < 4; ni++) {
                int c = wc * 32 + ni * 8 + group;
                bf[ni][0] = __float_as_uint(Bs[kk * BSTR + c]);
                bf[ni][1] = __float_as_uint(Bs[(kk + 4) * BSTR + c]);
            }
            #pragma unroll
            for (int mi = 0; mi < 4; mi++)
                #pragma unroll
                for (int ni = 0; ni < 4; ni++)
                    mma1688(acc[mi][ni], af[mi], bf[ni]);
        }
    };

    // prologue: stages 0,1 in flight
    ldgsts(0, 0);
    if (KT > 1) ldgsts(1, BK);
    cp_wait<1>();
    __syncthreads();

    for (int kt = 0; kt < KT; kt++) {
        compute(sm + (kt % NSTAGE) * STAGE_FLT);
        if (kt + 2 < KT) {
            ldgsts((kt + 2) % NSTAGE, (kt + 2) * BK);
            cp_wait<1>();
        } else {
            cp_wait<0>();
        }
        __syncthreads();
    }

    // ---- epilogue ----
    #pragma unroll
    for (int mi = 0; mi < 4; mi++) {
        #pragma unroll
        for (int ni = 0; ni < 4; ni++) {
            const int cg = col0 + wc * 32 + ni * 8 + tig * 2;
            #pragma unroll
            for (int half = 0; half < 2; half++) {
                const size_t r = (size_t)row0 + wr * 64 + mi * 16 + group + half * 8;
                float2 v;
                #pragma unroll
                for (int q = 0; q < 2; q++) {
                    int c = cg + q;
                    float x = acc[mi][ni][half * 2 + q] + __ldg(&bias[c]);
                    if (MODE == 0) { if (c >= 1280) x = fmaxf(x, 0.0f); }
                    if (MODE == 1) { x = to_tf32(fmaxf(x, 0.0f)); }
                    if (MODE == 2) {
                        float rr = __ldg(&resp[r * CAT + 1280 + c]);
                        x = (rr + x) * g_bnscale[c] + g_bnbias[c];
                    }
                    (&v.x)[q] = x;
                }
                *reinterpret_cast<float2*>(&C[r * Nn + cg]) = v;
            }
        }
    }
}

// ---------------------------------------------------------------------------
// Per-voxel head attention: 256 threads/voxel, shuffle softmax.
// Output tf32-rounded (consumed by cp.async GEMM2).
// ---------------------------------------------------------------------------
__global__ __launch_bounds__(256)
void attn_kernel(const float* __restrict__ qkvc, float* __restrict__ out)
{
    __shared__ float qk[QK * 2];           // q then k
    __shared__ float vs[VD];
    __shared__ float prob[NH][NH + 1];

    const size_t vox = blockIdx.x;
    const int t = threadIdx.x;
    const float4* base4 = reinterpret_cast<const float4*>(qkvc + vox * CAT);

    reinterpret_cast<float4*>(qk)[t] = base4[t];            // 256 f4 = q+k
    if (t < 64) reinterpret_cast<float4*>(vs)[t] = base4[256 + t];
    __syncthreads();

    const int h = t >> 4;
    const int g = t & 15;

    float s = 0.0f;
    const float* qh = &qk[h * DK];
    const float* kg = &qk[QK + g * DK];
    #pragma unroll
    for (int d = 0; d < DK; d++) s += qh[d] * kg[d];
    s *= 0.17677669529663687f;                // 1/sqrt(32)

    // softmax over g within each 16-lane segment
    float mx = s;
    #pragma unroll
    for (int m = 8; m > 0; m >>= 1)
        mx = fmaxf(mx, __shfl_xor_sync(0xffffffffu, mx, m, 16));
    float e = __expf(s - mx);
    float sum = e;
    #pragma unroll
    for (int m = 8; m > 0; m >>= 1)
        sum += __shfl_xor_sync(0xffffffffu, sum, m, 16);
    prob[h][g] = e / sum;
    __syncthreads();

    float o = 0.0f;
    #pragma unroll
    for (int j = 0; j < NH; j++) o += prob[h][j] * vs[j * DV + g];
    out[vox * VD + h * DV + g] = to_tf32(o);
}

// ---------------------------------------------------------------------------
// Launch
// ---------------------------------------------------------------------------
extern "C" void kernel_launch(void* const* d_in, const int* in_sizes, int n_in,
                              void* d_out, int out_size)
{
    const float* x     = (const float*)d_in[0];
    const float* Wq    = (const float*)d_in[1];
    const float* bq    = (const float*)d_in[2];
    const float* Wk    = (const float*)d_in[3];
    const float* bk    = (const float*)d_in[4];
    const float* Wv    = (const float*)d_in[5];
    const float* bv    = (const float*)d_in[6];
    const float* W1    = (const float*)d_in[7];
    const float* b1    = (const float*)d_in[8];
    const float* Wo    = (const float*)d_in[9];
    const float* bo    = (const float*)d_in[10];
    const float* Wc    = (const float*)d_in[11];
    const float* bc    = (const float*)d_in[12];
    const float* gamma = (const float*)d_in[13];
    const float* beta  = (const float*)d_in[14];
    const float* mu    = (const float*)d_in[15];
    const float* var   = (const float*)d_in[16];
    float* out = (float*)d_out;

    void* p;
    cudaGetSymbolAddress(&p, g_Wcat);  float* Wcat = (float*)p;
    cudaGetSymbolAddress(&p, g_W1r);   float* W1r  = (float*)p;
    cudaGetSymbolAddress(&p, g_Wor);   float* Wor  = (float*)p;
    cudaGetSymbolAddress(&p, g_bcat);  float* bcat = (float*)p;
    cudaGetSymbolAddress(&p, g_xr);    float* xr   = (float*)p;
    cudaGetSymbolAddress(&p, g_qkvc);  float* qkvc = (float*)p;
    cudaGetSymbolAddress(&p, g_attn);  float* attn = (float*)p;
    cudaGetSymbolAddress(&p, g_inter); float* inter = (float*)p;

    const int SMEM = NSTAGE * STAGE_BYTES;   // 107520
    cudaFuncSetAttribute(gemm_mma<0>, cudaFuncAttributeMaxDynamicSharedMemorySize, SMEM);
    cudaFuncSetAttribute(gemm_mma<1>, cudaFuncAttributeMaxDynamicSharedMemorySize, SMEM);
    cudaFuncSetAttribute(gemm_mma<2>, cudaFuncAttributeMaxDynamicSharedMemorySize, SMEM);

    pack_kernel<<<512, 256>>>(Wq, bq, Wk, bk, Wv, bv, W1, Wo, Wc, bc,
                              gamma, beta, mu, var);
    round_x_kernel<<<4096, 256>>>((const float4*)x, (float4*)xr);

    // qkvc = xr @ Wcat + bcat (relu on res cols)
    {
        dim3 grid(CAT / BN, NVOX / BM);
        gemm_mma<0><<<grid, 256, SMEM>>>(xr, Wcat, qkvc, CAT, CIN, bcat, nullptr);
    }

    attn_kernel<<<NVOX, 256>>>(qkvc, attn);

    // inter = relu(attn @ W1 + b1), tf32-rounded
    {
        dim3 grid(FF / BN, NVOX / BM);
        gemm_mma<1><<<grid, 256, SMEM>>>(attn, W1r, inter, FF, VD, b1, nullptr);
    }

    // out = (res + inter @ Wo + bo) * bnscale + bnbias
    {
        dim3 grid(VD / BN, NVOX / BM);
        gemm_mma<2><<<grid, 256, SMEM>>>(inter, Wor, out, VD, FF, bo, qkvc);
    }
}

// round 6
// speedup vs baseline: 5.3211x; 2.0881x over previous
#include <cuda_runtime.h>
#include <cuda_fp16.h>
#include <cstdint>
#include <math.h>

// ---------------------------------------------------------------------------
// Problem constants
// ---------------------------------------------------------------------------
#define NVOX   131072
#define CIN    256
#define NH     16
#define DK     32
#define DV     16
#define QK     512
#define VD     256
#define CAT    1536
#define QKV    1280          // q(512)|k(512)|v(256) fp16 buffer width
#define FF     1024

// ---------------------------------------------------------------------------
// Device scratch
// ---------------------------------------------------------------------------
__device__ __half g_WcatT[CAT * CIN];        // [1536,256] K-major fp16
__device__ __half g_W1T[FF * VD];            // [1024,256]
__device__ __half g_WoT[VD * FF];            // [256,1024]
__device__ float  g_bcat[CAT];
__device__ float  g_bnscale[VD];
__device__ float  g_bnbias[VD];
__device__ __half g_xh[(size_t)NVOX * CIN];
__device__ __half g_qkvh[(size_t)NVOX * QKV];
__device__ float  g_res[(size_t)NVOX * VD];  // residual branch, f32
__device__ __half g_attnh[(size_t)NVOX * VD];
__device__ __half g_interh[(size_t)NVOX * FF];

// ---------------------------------------------------------------------------
// PTX helpers
// ---------------------------------------------------------------------------
__device__ __forceinline__ uint32_t smem_u32(const void* p) {
    uint32_t a;
    asm("{ .reg .u64 t; cvta.to.shared.u64 t, %1; cvt.u32.u64 %0, t; }"
        : "=r"(a) : "l"(p));
    return a;
}
__device__ __forceinline__ void cp16(uint32_t dst, const void* src) {
    asm volatile("cp.async.cg.shared.global [%0], [%1], 16;"
                 :: "r"(dst), "l"(src) : "memory");
}
__device__ __forceinline__ void cp_commit() {
    asm volatile("cp.async.commit_group;" ::: "memory");
}
template<int N>
__device__ __forceinline__ void cp_wait() {
    asm volatile("cp.async.wait_group %0;" :: "n"(N) : "memory");
}
#define LDSM4(R, addr) \
    asm volatile("ldmatrix.sync.aligned.m8n8.x4.shared.b16 {%0,%1,%2,%3}, [%4];" \
                 : "=r"((R)[0]), "=r"((R)[1]), "=r"((R)[2]), "=r"((R)[3]) \
                 : "r"(addr))

__device__ __forceinline__ void mma16816(float* d, const uint32_t* a,
                                         uint32_t b0, uint32_t b1) {
    asm volatile(
        "mma.sync.aligned.m16n8k16.row.col.f32.f16.f16.f32 "
        "{%0,%1,%2,%3}, {%4,%5,%6,%7}, {%8,%9}, {%0,%1,%2,%3};"
        : "+f"(d[0]), "+f"(d[1]), "+f"(d[2]), "+f"(d[3])
        : "r"(a[0]), "r"(a[1]), "r"(a[2]), "r"(a[3]), "r"(b0), "r"(b1));
}

// Swizzled byte offset for (row 0..127, chunk16B 0..3) within an 8KB tile.
// Physical rows of 128B (8 chunks); conflict-free for ldmatrix quadrants.
__device__ __forceinline__ int swz(int r, int c) {
    return ((r >> 1) << 7) + (((((r & 1) << 2) | c) ^ ((r >> 1) & 7)) << 4);
}

// ---------------------------------------------------------------------------
// Pack: weights -> fp16 K-major transposes; biases; BN fold
// ---------------------------------------------------------------------------
__global__ void pack_kernel(const float* __restrict__ Wq, const float* __restrict__ bq,
                            const float* __restrict__ Wk, const float* __restrict__ bk,
                            const float* __restrict__ Wv, const float* __restrict__ bv,
                            const float* __restrict__ W1,
                            const float* __restrict__ Wo,
                            const float* __restrict__ Wc, const float* __restrict__ bc,
                            const float* __restrict__ gamma, const float* __restrict__ beta,
                            const float* __restrict__ mu, const float* __restrict__ var)
{
    int idx = blockIdx.x * blockDim.x + threadIdx.x;
    int st = gridDim.x * blockDim.x;
    for (int i = idx; i < CAT * CIN; i += st) {
        int n = i >> 8, k = i & 255;
        float w;
        if (n < 512)       w = Wq[k * 512 + n];
        else if (n < 1024) w = Wk[k * 512 + (n - 512)];
        else if (n < 1280) w = Wv[k * 256 + (n - 1024)];
        else               w = Wc[k * 256 + (n - 1280)];
        g_WcatT[i] = __float2half_rn(w);
    }
    for (int i = idx; i < FF * VD; i += st) {
        int n = i >> 8, k = i & 255;
        g_W1T[i] = __float2half_rn(W1[k * FF + n]);
    }
    for (int i = idx; i < VD * FF; i += st) {
        int n = i >> 10, k = i & 1023;
        g_WoT[i] = __float2half_rn(Wo[k * VD + n]);
    }
    for (int i = idx; i < CAT; i += st) {
        float b;
        if (i < 512)       b = bq[i];
        else if (i < 1024) b = bk[i - 512];
        else if (i < 1280) b = bv[i - 1024];
        else               b = bc[i - 1280];
        g_bcat[i] = b;
    }
    for (int i = idx; i < VD; i += st) {
        float s = gamma[i] * rsqrtf(var[i] + 1e-6f);
        g_bnscale[i] = s;
        g_bnbias[i]  = beta[i] - mu[i] * s;
    }
}

// x (f32) -> fp16
__global__ void x2h_kernel(const float4* __restrict__ in, uint2* __restrict__ out)
{
    const int n4 = NVOX * CIN / 4;
    int idx = blockIdx.x * blockDim.x + threadIdx.x;
    int st = gridDim.x * blockDim.x;
    for (int i = idx; i < n4; i += st) {
        float4 v = in[i];
        __half2 h0 = __floats2half2_rn(v.x, v.y);
        __half2 h1 = __floats2half2_rn(v.z, v.w);
        uint2 w;
        w.x = *reinterpret_cast<uint32_t*>(&h0);
        w.y = *reinterpret_cast<uint32_t*>(&h1);
        out[i] = w;
    }
}

// ---------------------------------------------------------------------------
// fp16 mma GEMM: C[M, Nn] = A[M,K] @ BT[Nn,K]^T
// BM=BN=128, BK=32, 4-stage cp.async, ldmatrix fragments.
//   MODE 0: cols<1280 -> fp16 qkv buffer (stride 1280); cols>=1280 -> relu f32 res
//   MODE 1: relu -> fp16
//   MODE 2: (res + acc + bias)*bns + bnb -> f32
// ---------------------------------------------------------------------------
#define STAGE_BYTES 16384
#define NSTAGE 4

template<int MODE>
__global__ __launch_bounds__(256, 2)
void gemm_h(const __half* __restrict__ A, const __half* __restrict__ BT,
            void* __restrict__ Cv, float* __restrict__ resf,
            int Nn, int K, const float* __restrict__ bias)
{
    extern __shared__ char sm[];
    const uint32_t smemU = smem_u32(sm);

    const int tid  = threadIdx.x;
    const int wid  = tid >> 5;
    const int lane = tid & 31;
    const int wr = wid >> 2;          // 0..1
    const int wc = wid & 3;           // 0..3
    const int group = lane >> 2;      // 0..7
    const int tig = lane & 3;         // 0..3

    const int row0 = blockIdx.y * 128;
    const int col0 = blockIdx.x * 128;
    const int KT = K / 32;

    // ldmatrix per-lane offsets (within an 8KB tile)
    int off_a[4][2], off_b[2][2];
    {
        int ar = lane & 15, ac = lane >> 4;
        #pragma unroll
        for (int mi = 0; mi < 4; mi++)
            #pragma unroll
            for (int ks = 0; ks < 2; ks++)
                off_a[mi][ks] = swz(wr * 64 + mi * 16 + ar, 2 * ks + ac);
        int br = (lane & 7) + (lane >> 4) * 8, bc2 = (lane >> 3) & 1;
        #pragma unroll
        for (int nip = 0; nip < 2; nip++)
            #pragma unroll
            for (int ks = 0; ks < 2; ks++)
                off_b[nip][ks] = swz(wc * 32 + nip * 16 + br, 2 * ks + bc2);
    }

    float acc[4][4][4];
    #pragma unroll
    for (int mi = 0; mi < 4; mi++)
        #pragma unroll
        for (int ni = 0; ni < 4; ni++)
            #pragma unroll
            for (int r = 0; r < 4; r++) acc[mi][ni][r] = 0.0f;

    auto ldgsts = [&](int stage, int k0) {
        const uint32_t aS = smemU + stage * STAGE_BYTES;
        const uint32_t bS = aS + 8192;
        #pragma unroll
        for (int i = 0; i < 2; i++) {
            int idx = tid + 256 * i;
            int r = idx >> 2, c = idx & 3;
            cp16(aS + swz(r, c), &A[(size_t)(row0 + r) * K + k0 + c * 8]);
            cp16(bS + swz(r, c), &BT[(size_t)(col0 + r) * K + k0 + c * 8]);
        }
        cp_commit();
    };

    auto compute = [&](int stage) {
        const uint32_t aS = smemU + stage * STAGE_BYTES;
        const uint32_t bS = aS + 8192;
        #pragma unroll
        for (int ks = 0; ks < 2; ks++) {
            uint32_t af[4][4], bf[2][4];
            #pragma unroll
            for (int mi = 0; mi < 4; mi++) LDSM4(af[mi], aS + off_a[mi][ks]);
            #pragma unroll
            for (int nip = 0; nip < 2; nip++) LDSM4(bf[nip], bS + off_b[nip][ks]);
            #pragma unroll
            for (int mi = 0; mi < 4; mi++)
                #pragma unroll
                for (int ni = 0; ni < 4; ni++) {
                    const int nip = ni >> 1, h = ni & 1;
                    mma16816(acc[mi][ni], af[mi], bf[nip][h * 2], bf[nip][h * 2 + 1]);
                }
        }
    };

    // prologue: 3 stages in flight
    ldgsts(0, 0);
    ldgsts(1, 32);
    ldgsts(2, 64);
    cp_wait<2>();
    __syncthreads();

    for (int kt = 0; kt < KT; kt++) {
        compute(kt & 3);
        if (kt + 3 < KT) {
            ldgsts((kt + 3) & 3, (kt + 3) * 32);
            cp_wait<2>();
        } else {
            cp_wait<0>();
        }
        __syncthreads();
    }

    // ---- epilogue ----
    __half* Ch = (__half*)Cv;
    float*  Cf = (float*)Cv;
    #pragma unroll
    for (int mi = 0; mi < 4; mi++) {
        #pragma unroll
        for (int ni = 0; ni < 4; ni++) {
            const int cg = col0 + wc * 32 + ni * 8 + tig * 2;
            const float bi0 = __ldg(&bias[cg]);
            const float bi1 = __ldg(&bias[cg + 1]);
            #pragma unroll
            for (int hf = 0; hf < 2; hf++) {
                const size_t r = (size_t)row0 + wr * 64 + mi * 16 + group + hf * 8;
                float v0 = acc[mi][ni][hf * 2 + 0] + bi0;
                float v1 = acc[mi][ni][hf * 2 + 1] + bi1;
                if (MODE == 0) {
                    if (col0 < QKV) {
                        __half2 h = __floats2half2_rn(v0, v1);
                        *reinterpret_cast<uint32_t*>(&Ch[r * QKV + cg]) =
                            *reinterpret_cast<uint32_t*>(&h);
                    } else {
                        float2 f = make_float2(fmaxf(v0, 0.0f), fmaxf(v1, 0.0f));
                        *reinterpret_cast<float2*>(&resf[r * VD + (cg - QKV)]) = f;
                    }
                }
                if (MODE == 1) {
                    __half2 h = __floats2half2_rn(fmaxf(v0, 0.0f), fmaxf(v1, 0.0f));
                    *reinterpret_cast<uint32_t*>(&Ch[r * Nn + cg]) =
                        *reinterpret_cast<uint32_t*>(&h);
                }
                if (MODE == 2) {
                    float2 rr = *reinterpret_cast<const float2*>(&resf[r * VD + cg]);
                    float2 f;
                    f.x = (rr.x + v0) * g_bnscale[cg]     + g_bnbias[cg];
                    f.y = (rr.y + v1) * g_bnscale[cg + 1] + g_bnbias[cg + 1];
                    *reinterpret_cast<float2*>(&Cf[r * Nn + cg]) = f;
                }
            }
        }
    }
}

// ---------------------------------------------------------------------------
// Per-voxel head attention (fp16 in/out, f32 math), shuffle softmax
// ---------------------------------------------------------------------------
__global__ __launch_bounds__(256)
void attn_kernel(const __half* __restrict__ qkvh, __half* __restrict__ outh)
{
    __shared__ __half qk[QK * 2];
    __shared__ __half vs[VD];
    __shared__ float prob[NH][NH + 1];

    const size_t vox = blockIdx.x;
    const int t = threadIdx.x;
    const uint4* src = reinterpret_cast<const uint4*>(qkvh + vox * QKV);

    if (t < 160) {
        uint4 w = src[t];
        if (t < 128) reinterpret_cast<uint4*>(qk)[t] = w;
        else         reinterpret_cast<uint4*>(vs)[t - 128] = w;
    }
    __syncthreads();

    const int h = t >> 4;
    const int g = t & 15;

    const __half2* q2 = reinterpret_cast<const __half2*>(qk) + h * 16;
    const __half2* k2 = reinterpret_cast<const __half2*>(qk) + 256 + g * 16;
    float s = 0.0f;
    #pragma unroll
    for (int d = 0; d < 16; d++) {
        float2 a = __half22float2(q2[d]);
        float2 b = __half22float2(k2[d]);
        s += a.x * b.x + a.y * b.y;
    }
    s *= 0.17677669529663687f;   // 1/sqrt(32)

    float mx = s;
    #pragma unroll
    for (int m = 8; m > 0; m >>= 1)
        mx = fmaxf(mx, __shfl_xor_sync(0xffffffffu, mx, m, 16));
    float e = __expf(s - mx);
    float sum = e;
    #pragma unroll
    for (int m = 8; m > 0; m >>= 1)
        sum += __shfl_xor_sync(0xffffffffu, sum, m, 16);
    prob[h][g] = e / sum;
    __syncthreads();

    float o = 0.0f;
    #pragma unroll
    for (int j = 0; j < NH; j++)
        o += prob[h][j] * __half2float(vs[j * DV + g]);
    outh[vox * VD + h * DV + g] = __float2half_rn(o);
}

// ---------------------------------------------------------------------------
// Launch
// ---------------------------------------------------------------------------
extern "C" void kernel_launch(void* const* d_in, const int* in_sizes, int n_in,
                              void* d_out, int out_size)
{
    const float* x     = (const float*)d_in[0];
    const float* Wq    = (const float*)d_in[1];
    const float* bq    = (const float*)d_in[2];
    const float* Wk    = (const float*)d_in[3];
    const float* bk    = (const float*)d_in[4];
    const float* Wv    = (const float*)d_in[5];
    const float* bv    = (const float*)d_in[6];
    const float* W1    = (const float*)d_in[7];
    const float* b1    = (const float*)d_in[8];
    const float* Wo    = (const float*)d_in[9];
    const float* bo    = (const float*)d_in[10];
    const float* Wc    = (const float*)d_in[11];
    const float* bc    = (const float*)d_in[12];
    const float* gamma = (const float*)d_in[13];
    const float* beta  = (const float*)d_in[14];
    const float* mu    = (const float*)d_in[15];
    const float* var   = (const float*)d_in[16];
    float* out = (float*)d_out;

    void* p;
    cudaGetSymbolAddress(&p, g_WcatT);  __half* WcatT = (__half*)p;
    cudaGetSymbolAddress(&p, g_W1T);    __half* W1T   = (__half*)p;
    cudaGetSymbolAddress(&p, g_WoT);    __half* WoT   = (__half*)p;
    cudaGetSymbolAddress(&p, g_bcat);   float*  bcat  = (float*)p;
    cudaGetSymbolAddress(&p, g_xh);     __half* xh    = (__half*)p;
    cudaGetSymbolAddress(&p, g_qkvh);   __half* qkvh  = (__half*)p;
    cudaGetSymbolAddress(&p, g_res);    float*  resf  = (float*)p;
    cudaGetSymbolAddress(&p, g_attnh);  __half* attnh = (__half*)p;
    cudaGetSymbolAddress(&p, g_interh); __half* interh = (__half*)p;

    const int SMEM = NSTAGE * STAGE_BYTES;   // 65536
    cudaFuncSetAttribute(gemm_h<0>, cudaFuncAttributeMaxDynamicSharedMemorySize, SMEM);
    cudaFuncSetAttribute(gemm_h<1>, cudaFuncAttributeMaxDynamicSharedMemorySize, SMEM);
    cudaFuncSetAttribute(gemm_h<2>, cudaFuncAttributeMaxDynamicSharedMemorySize, SMEM);

    pack_kernel<<<512, 256>>>(Wq, bq, Wk, bk, Wv, bv, W1, Wo, Wc, bc,
                              gamma, beta, mu, var);
    x2h_kernel<<<4096, 256>>>((const float4*)x, (uint2*)xh);

    // qkv (fp16) + res (f32) = x @ Wcat + bcat
    {
        dim3 grid(CAT / 128, NVOX / 128);
        gemm_h<0><<<grid, 256, SMEM>>>(xh, WcatT, qkvh, resf, QKV, CIN, bcat);
    }

    attn_kernel<<<NVOX, 256>>>(qkvh, attnh);

    // inter = relu(attn @ W1 + b1) fp16
    {
        dim3 grid(FF / 128, NVOX / 128);
        gemm_h<1><<<grid, 256, SMEM>>>(attnh, W1T, interh, nullptr, FF, VD, b1);
    }

    // out = (res + inter @ Wo + bo) * bnscale + bnbias
    {
        dim3 grid(VD / 128, NVOX / 128);
        gemm_h<2><<<grid, 256, SMEM>>>(interh, WoT, out, resf, VD, FF, bo);
    }
}

// round 8
// speedup vs baseline: 7.4045x; 1.3915x over previous
#include <cuda_runtime.h>
#include <cuda_fp16.h>
#include <cstdint>
#include <math.h>

// ---------------------------------------------------------------------------
// Problem constants
// ---------------------------------------------------------------------------
#define NVOX   131072
#define CIN    256
#define NH     16
#define DK     32
#define DV     16
#define QK     512
#define VD     256
#define CAT    1536
#define QKV    1280          // q(512)|k(512)|v(256) fp16 buffer width
#define FF     1024

// ---------------------------------------------------------------------------
// Device scratch
// ---------------------------------------------------------------------------
__device__ __half g_WcatT[CAT * CIN];        // [1536,256] K-major fp16
__device__ __half g_W1T[FF * VD];            // [1024,256]
__device__ __half g_WoT[VD * FF];            // [256,1024]
__device__ float  g_bcat[CAT];
__device__ float  g_bnscale[VD];
__device__ float  g_bnbias[VD];
__device__ __half g_xh[(size_t)NVOX * CIN];
__device__ __half g_qkvh[(size_t)NVOX * QKV];
__device__ float  g_res[(size_t)NVOX * VD];  // residual branch, f32
__device__ __half g_attnh[(size_t)NVOX * VD];
__device__ __half g_interh[(size_t)NVOX * FF];

// ---------------------------------------------------------------------------
// PTX helpers
// ---------------------------------------------------------------------------
__device__ __forceinline__ uint32_t smem_u32(const void* p) {
    uint32_t a;
    asm("{ .reg .u64 t; cvta.to.shared.u64 t, %1; cvt.u32.u64 %0, t; }"
        : "=r"(a) : "l"(p));
    return a;
}
__device__ __forceinline__ void cp16(uint32_t dst, const void* src) {
    asm volatile("cp.async.cg.shared.global [%0], [%1], 16;"
                 :: "r"(dst), "l"(src) : "memory");
}
__device__ __forceinline__ void cp_commit() {
    asm volatile("cp.async.commit_group;" ::: "memory");
}
template<int N>
__device__ __forceinline__ void cp_wait() {
    asm volatile("cp.async.wait_group %0;" :: "n"(N) : "memory");
}
__device__ __forceinline__ uint32_t lds32(uint32_t a) {
    uint32_t v; asm volatile("ld.shared.b32 %0, [%1];" : "=r"(v) : "r"(a)); return v;
}
__device__ __forceinline__ uint32_t lds16(uint32_t a) {
    uint32_t v; asm volatile("ld.shared.u16 %0, [%1];" : "=r"(v) : "r"(a)); return v;
}
#define LDSM4(R, addr) \
    asm volatile("ldmatrix.sync.aligned.m8n8.x4.shared.b16 {%0,%1,%2,%3}, [%4];" \
                 : "=r"((R)[0]), "=r"((R)[1]), "=r"((R)[2]), "=r"((R)[3]) \
                 : "r"(addr))

__device__ __forceinline__ void mma16816(float* d, const uint32_t* a,
                                         uint32_t b0, uint32_t b1) {
    asm volatile(
        "mma.sync.aligned.m16n8k16.row.col.f32.f16.f16.f32 "
        "{%0,%1,%2,%3}, {%4,%5,%6,%7}, {%8,%9}, {%0,%1,%2,%3};"
        : "+f"(d[0]), "+f"(d[1]), "+f"(d[2]), "+f"(d[3])
        : "r"(a[0]), "r"(a[1]), "r"(a[2]), "r"(a[3]), "r"(b0), "r"(b1));
}

// Swizzled byte offset for (row 0..127, chunk16B 0..3) within an 8KB tile
__device__ __forceinline__ int swz(int r, int c) {
    return ((r >> 1) << 7) + (((((r & 1) << 2) | c) ^ ((r >> 1) & 7)) << 4);
}

// ---------------------------------------------------------------------------
// Pack: weights -> fp16 K-major transposes; biases; BN fold
// ---------------------------------------------------------------------------
__global__ void pack_kernel(const float* __restrict__ Wq, const float* __restrict__ bq,
                            const float* __restrict__ Wk, const float* __restrict__ bk,
                            const float* __restrict__ Wv, const float* __restrict__ bv,
                            const float* __restrict__ W1,
                            const float* __restrict__ Wo,
                            const float* __restrict__ Wc, const float* __restrict__ bc,
                            const float* __restrict__ gamma, const float* __restrict__ beta,
                            const float* __restrict__ mu, const float* __restrict__ var)
{
    int idx = blockIdx.x * blockDim.x + threadIdx.x;
    int st = gridDim.x * blockDim.x;
    for (int i = idx; i < CAT * CIN; i += st) {
        int n = i >> 8, k = i & 255;
        float w;
        if (n < 512)       w = Wq[k * 512 + n];
        else if (n < 1024) w = Wk[k * 512 + (n - 512)];
        else if (n < 1280) w = Wv[k * 256 + (n - 1024)];
        else               w = Wc[k * 256 + (n - 1280)];
        g_WcatT[i] = __float2half_rn(w);
    }
    for (int i = idx; i < FF * VD; i += st) {
        int n = i >> 8, k = i & 255;
        g_W1T[i] = __float2half_rn(W1[k * FF + n]);
    }
    for (int i = idx; i < VD * FF; i += st) {
        int n = i >> 10, k = i & 1023;
        g_WoT[i] = __float2half_rn(Wo[k * VD + n]);
    }
    for (int i = idx; i < CAT; i += st) {
        float b;
        if (i < 512)       b = bq[i];
        else if (i < 1024) b = bk[i - 512];
        else if (i < 1280) b = bv[i - 1024];
        else               b = bc[i - 1280];
        g_bcat[i] = b;
    }
    for (int i = idx; i < VD; i += st) {
        float s = gamma[i] * rsqrtf(var[i] + 1e-6f);
        g_bnscale[i] = s;
        g_bnbias[i]  = beta[i] - mu[i] * s;
    }
}

// x (f32) -> fp16
__global__ void x2h_kernel(const float4* __restrict__ in, uint2* __restrict__ out)
{
    const int n4 = NVOX * CIN / 4;
    int idx = blockIdx.x * blockDim.x + threadIdx.x;
    int st = gridDim.x * blockDim.x;
    for (int i = idx; i < n4; i += st) {
        float4 v = in[i];
        __half2 h0 = __floats2half2_rn(v.x, v.y);
        __half2 h1 = __floats2half2_rn(v.z, v.w);
        uint2 w;
        w.x = *reinterpret_cast<uint32_t*>(&h0);
        w.y = *reinterpret_cast<uint32_t*>(&h1);
        out[i] = w;
    }
}

// ---------------------------------------------------------------------------
// fp16 mma GEMM (unchanged from round 6)
// ---------------------------------------------------------------------------
#define STAGE_BYTES 16384
#define NSTAGE 4

template<int MODE>
__global__ __launch_bounds__(256, 2)
void gemm_h(const __half* __restrict__ A, const __half* __restrict__ BT,
            void* __restrict__ Cv, float* __restrict__ resf,
            int Nn, int K, const float* __restrict__ bias)
{
    extern __shared__ char sm[];
    const uint32_t smemU = smem_u32(sm);

    const int tid  = threadIdx.x;
    const int wid  = tid >> 5;
    const int lane = tid & 31;
    const int wr = wid >> 2;
    const int wc = wid & 3;
    const int group = lane >> 2;
    const int tig = lane & 3;

    const int row0 = blockIdx.y * 128;
    const int col0 = blockIdx.x * 128;
    const int KT = K / 32;

    int off_a[4][2], off_b[2][2];
    {
        int ar = lane & 15, ac = lane >> 4;
        #pragma unroll
        for (int mi = 0; mi < 4; mi++)
            #pragma unroll
            for (int ks = 0; ks < 2; ks++)
                off_a[mi][ks] = swz(wr * 64 + mi * 16 + ar, 2 * ks + ac);
        int br = (lane & 7) + (lane >> 4) * 8, bc2 = (lane >> 3) & 1;
        #pragma unroll
        for (int nip = 0; nip < 2; nip++)
            #pragma unroll
            for (int ks = 0; ks < 2; ks++)
                off_b[nip][ks] = swz(wc * 32 + nip * 16 + br, 2 * ks + bc2);
    }

    float acc[4][4][4];
    #pragma unroll
    for (int mi = 0; mi < 4; mi++)
        #pragma unroll
        for (int ni = 0; ni < 4; ni++)
            #pragma unroll
            for (int r = 0; r < 4; r++) acc[mi][ni][r] = 0.0f;

    auto ldgsts = [&](int stage, int k0) {
        const uint32_t aS = smemU + stage * STAGE_BYTES;
        const uint32_t bS = aS + 8192;
        #pragma unroll
        for (int i = 0; i < 2; i++) {
            int idx = tid + 256 * i;
            int r = idx >> 2, c = idx & 3;
            cp16(aS + swz(r, c), &A[(size_t)(row0 + r) * K + k0 + c * 8]);
            cp16(bS + swz(r, c), &BT[(size_t)(col0 + r) * K + k0 + c * 8]);
        }
        cp_commit();
    };

    auto compute = [&](int stage) {
        const uint32_t aS = smemU + stage * STAGE_BYTES;
        const uint32_t bS = aS + 8192;
        #pragma unroll
        for (int ks = 0; ks < 2; ks++) {
            uint32_t af[4][4], bf[2][4];
            #pragma unroll
            for (int mi = 0; mi < 4; mi++) LDSM4(af[mi], aS + off_a[mi][ks]);
            #pragma unroll
            for (int nip = 0; nip < 2; nip++) LDSM4(bf[nip], bS + off_b[nip][ks]);
            #pragma unroll
            for (int mi = 0; mi < 4; mi++)
                #pragma unroll
                for (int ni = 0; ni < 4; ni++) {
                    const int nip = ni >> 1, h = ni & 1;
                    mma16816(acc[mi][ni], af[mi], bf[nip][h * 2], bf[nip][h * 2 + 1]);
                }
        }
    };

    ldgsts(0, 0);
    ldgsts(1, 32);
    ldgsts(2, 64);
    cp_wait<2>();
    __syncthreads();

    for (int kt = 0; kt < KT; kt++) {
        compute(kt & 3);
        if (kt + 3 < KT) {
            ldgsts((kt + 3) & 3, (kt + 3) * 32);
            cp_wait<2>();
        } else {
            cp_wait<0>();
        }
        __syncthreads();
    }

    __half* Ch = (__half*)Cv;
    float*  Cf = (float*)Cv;
    #pragma unroll
    for (int mi = 0; mi < 4; mi++) {
        #pragma unroll
        for (int ni = 0; ni < 4; ni++) {
            const int cg = col0 + wc * 32 + ni * 8 + tig * 2;
            const float bi0 = __ldg(&bias[cg]);
            const float bi1 = __ldg(&bias[cg + 1]);
            #pragma unroll
            for (int hf = 0; hf < 2; hf++) {
                const size_t r = (size_t)row0 + wr * 64 + mi * 16 + group + hf * 8;
                float v0 = acc[mi][ni][hf * 2 + 0] + bi0;
                float v1 = acc[mi][ni][hf * 2 + 1] + bi1;
                if (MODE == 0) {
                    if (col0 < QKV) {
                        __half2 h = __floats2half2_rn(v0, v1);
                        *reinterpret_cast<uint32_t*>(&Ch[r * QKV + cg]) =
                            *reinterpret_cast<uint32_t*>(&h);
                    } else {
                        float2 f = make_float2(fmaxf(v0, 0.0f), fmaxf(v1, 0.0f));
                        *reinterpret_cast<float2*>(&resf[r * VD + (cg - QKV)]) = f;
                    }
                }
                if (MODE == 1) {
                    __half2 h = __floats2half2_rn(fmaxf(v0, 0.0f), fmaxf(v1, 0.0f));
                    *reinterpret_cast<uint32_t*>(&Ch[r * Nn + cg]) =
                        *reinterpret_cast<uint32_t*>(&h);
                }
                if (MODE == 2) {
                    float2 rr = *reinterpret_cast<const float2*>(&resf[r * VD + cg]);
                    float2 f;
                    f.x = (rr.x + v0) * g_bnscale[cg]     + g_bnbias[cg];
                    f.y = (rr.y + v1) * g_bnscale[cg + 1] + g_bnbias[cg + 1];
                    *reinterpret_cast<float2*>(&Cf[r * Nn + cg]) = f;
                }
            }
        }
    }
}

// ---------------------------------------------------------------------------
// Tensor-core attention: one warp per voxel, 8 voxels per 256-thread block.
// S = Q@K^T (m16n16k32), softmax in accumulators, O = P@V (m16n16k16).
// Q/K rows padded to 80B, V rows to 48B (conflict-free LDS patterns).
// ---------------------------------------------------------------------------
#define VOX_B   3328          // 1280 (Q) + 1280 (K) + 768 (V)
#define SCALE_S 0.17677669529663687f

__global__ __launch_bounds__(256)
void attn_mma_kernel(const __half* __restrict__ qkvh, __half* __restrict__ outh)
{
    __shared__ __align__(16) char sm[8 * VOX_B];
    const uint32_t smemU = smem_u32(sm);

    const int tid  = threadIdx.x;
    const int wid  = tid >> 5;
    const int lane = tid & 31;
    const size_t vox0 = (size_t)blockIdx.x * 8;

    // ---- stage 8 voxels of qkv into padded smem ----
    for (int i = tid; i < 1280; i += 256) {
        int slot = i >> 7;             // 1280/8 voxels -> careful: 160 per voxel
        slot = i / 160;
        int j = i - slot * 160;
        int off;
        if (j < 64)       off = (j >> 2) * 80 + (j & 3) * 16;
        else if (j < 128) off = 1280 + ((j - 64) >> 2) * 80 + ((j - 64) & 3) * 16;
        else              off = 2560 + ((j - 128) >> 1) * 48 + ((j - 128) & 1) * 16;
        cp16(smemU + slot * VOX_B + off, qkvh + (vox0 + slot) * QKV + j * 8);
    }
    cp_commit();
    cp_wait<0>();
    __syncthreads();

    const uint32_t qb = smemU + wid * VOX_B;
    const uint32_t kb = qb + 1280;
    const uint32_t vb = qb + 2560;
    const int g4 = lane >> 2;      // 0..7
    const int t4 = lane & 3;       // 0..3

    // ---- S = Q @ K^T ----
    float sacc[2][4];
    #pragma unroll
    for (int nt = 0; nt < 2; nt++)
        #pragma unroll
        for (int r = 0; r < 4; r++) sacc[nt][r] = 0.0f;

    #pragma unroll
    for (int ks = 0; ks < 2; ks++) {
        uint32_t a[4];
        a[0] = lds32(qb + g4 * 80       + ks * 32 + t4 * 4);
        a[1] = lds32(qb + (g4 + 8) * 80 + ks * 32 + t4 * 4);
        a[2] = lds32(qb + g4 * 80       + ks * 32 + t4 * 4 + 16);
        a[3] = lds32(qb + (g4 + 8) * 80 + ks * 32 + t4 * 4 + 16);
        #pragma unroll
        for (int nt = 0; nt < 2; nt++) {
            uint32_t b0 = lds32(kb + (nt * 8 + g4) * 80 + ks * 32 + t4 * 4);
            uint32_t b1 = lds32(kb + (nt * 8 + g4) * 80 + ks * 32 + t4 * 4 + 16);
            mma16816(sacc[nt], a, b0, b1);
        }
    }

    // ---- softmax over the 16 columns of each row ----
    // lane holds rows g4 (hf=0) and g4+8 (hf=1); cols 2*t4,2*t4+1 (+8 for nt=1)
    uint32_t af[4];
    #pragma unroll
    for (int hf = 0; hf < 2; hf++) {
        float v00 = sacc[0][hf * 2]     * SCALE_S;
        float v01 = sacc[0][hf * 2 + 1] * SCALE_S;
        float v10 = sacc[1][hf * 2]     * SCALE_S;
        float v11 = sacc[1][hf * 2 + 1] * SCALE_S;
        float mx = fmaxf(fmaxf(v00, v01), fmaxf(v10, v11));
        mx = fmaxf(mx, __shfl_xor_sync(0xffffffffu, mx, 1));
        mx = fmaxf(mx, __shfl_xor_sync(0xffffffffu, mx, 2));
        float e00 = __expf(v00 - mx), e01 = __expf(v01 - mx);
        float e10 = __expf(v10 - mx), e11 = __expf(v11 - mx);
        float sum = e00 + e01 + e10 + e11;
        sum += __shfl_xor_sync(0xffffffffu, sum, 1);
        sum += __shfl_xor_sync(0xffffffffu, sum, 2);
        float inv = 1.0f / sum;
        __half2 p0 = __floats2half2_rn(e00 * inv, e01 * inv);
        __half2 p1 = __floats2half2_rn(e10 * inv, e11 * inv);
        af[hf]     = *reinterpret_cast<uint32_t*>(&p0);   // A-frag: a0/a1 = k 0-7
        af[hf + 2] = *reinterpret_cast<uint32_t*>(&p1);   // a2/a3 = k 8-15
    }

    // ---- O = P @ V ----
    float oacc[2][4];
    #pragma unroll
    for (int nt = 0; nt < 2; nt++)
        #pragma unroll
        for (int r = 0; r < 4; r++) oacc[nt][r] = 0.0f;

    #pragma unroll
    for (int nt = 0; nt < 2; nt++) {
        uint32_t b[2];
        #pragma unroll
        for (int reg = 0; reg < 2; reg++) {
            int jr = 2 * t4 + reg * 8;
            uint32_t lo = lds16(vb + jr * 48       + (nt * 8 + g4) * 2);
            uint32_t hi = lds16(vb + (jr + 1) * 48 + (nt * 8 + g4) * 2);
            b[reg] = lo | (hi << 16);
        }
        mma16816(oacc[nt], af, b[0], b[1]);
    }

    // ---- store [NH x DV] fp16 ----
    __half* dst = outh + (vox0 + wid) * VD;
    #pragma unroll
    for (int nt = 0; nt < 2; nt++) {
        #pragma unroll
        for (int hf = 0; hf < 2; hf++) {
            __half2 h = __floats2half2_rn(oacc[nt][hf * 2], oacc[nt][hf * 2 + 1]);
            int r = g4 + 8 * hf;
            int c = nt * 8 + 2 * t4;
            *reinterpret_cast<uint32_t*>(&dst[r * DV + c]) =
                *reinterpret_cast<uint32_t*>(&h);
        }
    }
}

// ---------------------------------------------------------------------------
// Launch
// ---------------------------------------------------------------------------
extern "C" void kernel_launch(void* const* d_in, const int* in_sizes, int n_in,
                              void* d_out, int out_size)
{
    const float* x     = (const float*)d_in[0];
    const float* Wq    = (const float*)d_in[1];
    const float* bq    = (const float*)d_in[2];
    const float* Wk    = (const float*)d_in[3];
    const float* bk    = (const float*)d_in[4];
    const float* Wv    = (const float*)d_in[5];
    const float* bv    = (const float*)d_in[6];
    const float* W1    = (const float*)d_in[7];
    const float* b1    = (const float*)d_in[8];
    const float* Wo    = (const float*)d_in[9];
    const float* bo    = (const float*)d_in[10];
    const float* Wc    = (const float*)d_in[11];
    const float* bc    = (const float*)d_in[12];
    const float* gamma = (const float*)d_in[13];
    const float* beta  = (const float*)d_in[14];
    const float* mu    = (const float*)d_in[15];
    const float* var   = (const float*)d_in[16];
    float* out = (float*)d_out;

    void* p;
    cudaGetSymbolAddress(&p, g_WcatT);  __half* WcatT = (__half*)p;
    cudaGetSymbolAddress(&p, g_W1T);    __half* W1T   = (__half*)p;
    cudaGetSymbolAddress(&p, g_WoT);    __half* WoT   = (__half*)p;
    cudaGetSymbolAddress(&p, g_bcat);   float*  bcat  = (float*)p;
    cudaGetSymbolAddress(&p, g_xh);     __half* xh    = (__half*)p;
    cudaGetSymbolAddress(&p, g_qkvh);   __half* qkvh  = (__half*)p;
    cudaGetSymbolAddress(&p, g_res);    float*  resf  = (float*)p;
    cudaGetSymbolAddress(&p, g_attnh);  __half* attnh = (__half*)p;
    cudaGetSymbolAddress(&p, g_interh); __half* interh = (__half*)p;

    const int SMEM = NSTAGE * STAGE_BYTES;   // 65536
    cudaFuncSetAttribute(gemm_h<0>, cudaFuncAttributeMaxDynamicSharedMemorySize, SMEM);
    cudaFuncSetAttribute(gemm_h<1>, cudaFuncAttributeMaxDynamicSharedMemorySize, SMEM);
    cudaFuncSetAttribute(gemm_h<2>, cudaFuncAttributeMaxDynamicSharedMemorySize, SMEM);

    pack_kernel<<<512, 256>>>(Wq, bq, Wk, bk, Wv, bv, W1, Wo, Wc, bc,
                              gamma, beta, mu, var);
    x2h_kernel<<<4096, 256>>>((const float4*)x, (uint2*)xh);

    // qkv (fp16) + res (f32) = x @ Wcat + bcat
    {
        dim3 grid(CAT / 128, NVOX / 128);
        gemm_h<0><<<grid, 256, SMEM>>>(xh, WcatT, qkvh, resf, QKV, CIN, bcat);
    }

    attn_mma_kernel<<<NVOX / 8, 256>>>(qkvh, attnh);

    // inter = relu(attn @ W1 + b1) fp16
    {
        dim3 grid(FF / 128, NVOX / 128);
        gemm_h<1><<<grid, 256, SMEM>>>(attnh, W1T, interh, nullptr, FF, VD, b1);
    }

    // out = (res + inter @ Wo + bo) * bnscale + bnbias
    {
        dim3 grid(VD / 128, NVOX / 128);
        gemm_h<2><<<grid, 256, SMEM>>>(interh, WoT, out, resf, VD, FF, bo);
    }
}

// round 9
// speedup vs baseline: 7.9664x; 1.0759x over previous
#include <cuda_runtime.h>
#include <cuda_fp16.h>
#include <cstdint>
#include <math.h>

// ---------------------------------------------------------------------------
// Problem constants
// ---------------------------------------------------------------------------
#define NVOX   131072
#define CIN    256
#define NH     16
#define DK     32
#define DV     16
#define QK     512
#define VD     256
#define CAT    1536
#define QKV    1280          // q(512)|k(512)|v(256) fp16 buffer width
#define FF     1024

// ---------------------------------------------------------------------------
// Device scratch
// ---------------------------------------------------------------------------
__device__ __half g_WcatT[CAT * CIN];        // [1536,256] K-major fp16
__device__ __half g_W1T[FF * VD];            // [1024,256]
__device__ __half g_WoT[VD * FF];            // [256,1024]
__device__ float  g_bcat[CAT];
__device__ float  g_bnscale[VD];
__device__ float  g_bnbias[VD];
__device__ __half g_xh[(size_t)NVOX * CIN];
__device__ __half g_qkvh[(size_t)NVOX * QKV];
__device__ float  g_res[(size_t)NVOX * VD];  // residual branch, f32
__device__ __half g_attnh[(size_t)NVOX * VD];
__device__ __half g_interh[(size_t)NVOX * FF];

// ---------------------------------------------------------------------------
// PTX helpers
// ---------------------------------------------------------------------------
__device__ __forceinline__ uint32_t smem_u32(const void* p) {
    uint32_t a;
    asm("{ .reg .u64 t; cvta.to.shared.u64 t, %1; cvt.u32.u64 %0, t; }"
        : "=r"(a) : "l"(p));
    return a;
}
__device__ __forceinline__ void cp16(uint32_t dst, const void* src) {
    asm volatile("cp.async.cg.shared.global [%0], [%1], 16;"
                 :: "r"(dst), "l"(src) : "memory");
}
__device__ __forceinline__ void cp_commit() {
    asm volatile("cp.async.commit_group;" ::: "memory");
}
template<int N>
__device__ __forceinline__ void cp_wait() {
    asm volatile("cp.async.wait_group %0;" :: "n"(N) : "memory");
}
__device__ __forceinline__ uint32_t lds32(uint32_t a) {
    uint32_t v; asm volatile("ld.shared.b32 %0, [%1];" : "=r"(v) : "r"(a)); return v;
}
__device__ __forceinline__ uint32_t lds16(uint32_t a) {
    uint32_t v; asm volatile("ld.shared.u16 %0, [%1];" : "=r"(v) : "r"(a)); return v;
}
#define LDSM4(R, addr) \
    asm volatile("ldmatrix.sync.aligned.m8n8.x4.shared.b16 {%0,%1,%2,%3}, [%4];" \
                 : "=r"((R)[0]), "=r"((R)[1]), "=r"((R)[2]), "=r"((R)[3]) \
                 : "r"(addr))

__device__ __forceinline__ void mma16816(float* d, const uint32_t* a,
                                         uint32_t b0, uint32_t b1) {
    asm volatile(
        "mma.sync.aligned.m16n8k16.row.col.f32.f16.f16.f32 "
        "{%0,%1,%2,%3}, {%4,%5,%6,%7}, {%8,%9}, {%0,%1,%2,%3};"
        : "+f"(d[0]), "+f"(d[1]), "+f"(d[2]), "+f"(d[3])
        : "r"(a[0]), "r"(a[1]), "r"(a[2]), "r"(a[3]), "r"(b0), "r"(b1));
}

// Swizzled byte offset inside a 16KB stage tile: 128 rows x 8 chunks of 16B.
// chunk XOR (row & 7) -> conflict-free ldmatrix phases & cp.async stores.
__device__ __forceinline__ int swz128(int r, int c) {
    return (r << 7) | (((c ^ (r & 7)) & 7) << 4);
}
// Legacy 64B-row swizzle for the attention staging (8KB tile, 4 chunks/row)
__device__ __forceinline__ int swz(int r, int c) {
    return ((r >> 1) << 7) + (((((r & 1) << 2) | c) ^ ((r >> 1) & 7)) << 4);
}

// ---------------------------------------------------------------------------
// Pack: weights -> fp16 K-major transposes; biases; BN fold
// ---------------------------------------------------------------------------
__global__ void pack_kernel(const float* __restrict__ Wq, const float* __restrict__ bq,
                            const float* __restrict__ Wk, const float* __restrict__ bk,
                            const float* __restrict__ Wv, const float* __restrict__ bv,
                            const float* __restrict__ W1,
                            const float* __restrict__ Wo,
                            const float* __restrict__ Wc, const float* __restrict__ bc,
                            const float* __restrict__ gamma, const float* __restrict__ beta,
                            const float* __restrict__ mu, const float* __restrict__ var)
{
    int idx = blockIdx.x * blockDim.x + threadIdx.x;
    int st = gridDim.x * blockDim.x;
    for (int i = idx; i < CAT * CIN; i += st) {
        int n = i >> 8, k = i & 255;
        float w;
        if (n < 512)       w = Wq[k * 512 + n];
        else if (n < 1024) w = Wk[k * 512 + (n - 512)];
        else if (n < 1280) w = Wv[k * 256 + (n - 1024)];
        else               w = Wc[k * 256 + (n - 1280)];
        g_WcatT[i] = __float2half_rn(w);
    }
    for (int i = idx; i < FF * VD; i += st) {
        int n = i >> 8, k = i & 255;
        g_W1T[i] = __float2half_rn(W1[k * FF + n]);
    }
    for (int i = idx; i < VD * FF; i += st) {
        int n = i >> 10, k = i & 1023;
        g_WoT[i] = __float2half_rn(Wo[k * VD + n]);
    }
    for (int i = idx; i < CAT; i += st) {
        float b;
        if (i < 512)       b = bq[i];
        else if (i < 1024) b = bk[i - 512];
        else if (i < 1280) b = bv[i - 1024];
        else               b = bc[i - 1280];
        g_bcat[i] = b;
    }
    for (int i = idx; i < VD; i += st) {
        float s = gamma[i] * rsqrtf(var[i] + 1e-6f);
        g_bnscale[i] = s;
        g_bnbias[i]  = beta[i] - mu[i] * s;
    }
}

// x (f32) -> fp16
__global__ void x2h_kernel(const float4* __restrict__ in, uint2* __restrict__ out)
{
    const int n4 = NVOX * CIN / 4;
    int idx = blockIdx.x * blockDim.x + threadIdx.x;
    int st = gridDim.x * blockDim.x;
    for (int i = idx; i < n4; i += st) {
        float4 v = in[i];
        __half2 h0 = __floats2half2_rn(v.x, v.y);
        __half2 h1 = __floats2half2_rn(v.z, v.w);
        uint2 w;
        w.x = *reinterpret_cast<uint32_t*>(&h0);
        w.y = *reinterpret_cast<uint32_t*>(&h1);
        out[i] = w;
    }
}

// ---------------------------------------------------------------------------
// fp16 mma GEMM: BM=BN=128, BK=64, 3-stage cp.async, one sync per k-tile.
//   MODE 0: cols<1280 -> fp16 qkv (stride 1280); cols>=1280 -> relu f32 res
//   MODE 1: relu -> fp16
//   MODE 2: (res + acc + bias)*bns + bnb -> f32
// ---------------------------------------------------------------------------
#define BKT 64
#define STAGE_BYTES 32768       // A 16KB + B 16KB
#define NSTAGE 3

template<int MODE>
__global__ __launch_bounds__(256, 2)
void gemm_h(const __half* __restrict__ A, const __half* __restrict__ BT,
            void* __restrict__ Cv, float* __restrict__ resf,
            int Nn, int K, const float* __restrict__ bias)
{
    extern __shared__ char sm[];
    const uint32_t smemU = smem_u32(sm);

    const int tid  = threadIdx.x;
    const int wid  = tid >> 5;
    const int lane = tid & 31;
    const int wr = wid >> 2;          // 0..1
    const int wc = wid & 3;           // 0..3
    const int group = lane >> 2;      // 0..7
    const int tig = lane & 3;         // 0..3

    const int row0 = blockIdx.y * 128;
    const int col0 = blockIdx.x * 128;
    const int KT = K / BKT;

    float acc[4][4][4];
    #pragma unroll
    for (int mi = 0; mi < 4; mi++)
        #pragma unroll
        for (int ni = 0; ni < 4; ni++)
            #pragma unroll
            for (int r = 0; r < 4; r++) acc[mi][ni][r] = 0.0f;

    // 128 rows x 8 chunks(16B) per operand per stage; 4 cp16 each per thread
    const int ldr = tid >> 3;         // base row (0..31), +32*i
    const int ldc = tid & 7;          // chunk 0..7

    auto ldgsts = [&](int stage, int k0) {
        const uint32_t aS = smemU + stage * STAGE_BYTES;
        const uint32_t bS = aS + 16384;
        #pragma unroll
        for (int i = 0; i < 4; i++) {
            int r = ldr + 32 * i;
            cp16(aS + swz128(r, ldc), &A[(size_t)(row0 + r) * K + k0 + ldc * 8]);
            cp16(bS + swz128(r, ldc), &BT[(size_t)(col0 + r) * K + k0 + ldc * 8]);
        }
        cp_commit();
    };

    const int ar = lane & 15, ahi = lane >> 4;
    const int br = (lane & 7) + (lane >> 4) * 8, bhi = (lane >> 3) & 1;

    auto compute = [&](int stage) {
        const uint32_t aS = smemU + stage * STAGE_BYTES;
        const uint32_t bS = aS + 16384;
        #pragma unroll
        for (int ks = 0; ks < 4; ks++) {
            uint32_t af[4][4], bf[2][4];
            #pragma unroll
            for (int mi = 0; mi < 4; mi++)
                LDSM4(af[mi], aS + swz128(wr * 64 + mi * 16 + ar, ks * 2 + ahi));
            #pragma unroll
            for (int nip = 0; nip < 2; nip++)
                LDSM4(bf[nip], bS + swz128(wc * 32 + nip * 16 + br, ks * 2 + bhi));
            #pragma unroll
            for (int mi = 0; mi < 4; mi++)
                #pragma unroll
                for (int ni = 0; ni < 4; ni++) {
                    const int nip = ni >> 1, h = ni & 1;
                    mma16816(acc[mi][ni], af[mi], bf[nip][h * 2], bf[nip][h * 2 + 1]);
                }
        }
    };

    // prologue: 2 stages in flight
    ldgsts(0, 0);
    ldgsts(1, BKT);

    for (int kt = 0; kt < KT; kt++) {
        if (kt + 1 < KT) cp_wait<1>(); else cp_wait<0>();
        __syncthreads();
        compute(kt % NSTAGE);
        if (kt + 2 < KT) ldgsts((kt + 2) % NSTAGE, (kt + 2) * BKT);
    }

    // ---- epilogue ----
    __half* Ch = (__half*)Cv;
    float*  Cf = (float*)Cv;
    #pragma unroll
    for (int mi = 0; mi < 4; mi++) {
        #pragma unroll
        for (int ni = 0; ni < 4; ni++) {
            const int cg = col0 + wc * 32 + ni * 8 + tig * 2;
            const float bi0 = __ldg(&bias[cg]);
            const float bi1 = __ldg(&bias[cg + 1]);
            #pragma unroll
            for (int hf = 0; hf < 2; hf++) {
                const size_t r = (size_t)row0 + wr * 64 + mi * 16 + group + hf * 8;
                float v0 = acc[mi][ni][hf * 2 + 0] + bi0;
                float v1 = acc[mi][ni][hf * 2 + 1] + bi1;
                if (MODE == 0) {
                    if (col0 < QKV) {
                        __half2 h = __floats2half2_rn(v0, v1);
                        *reinterpret_cast<uint32_t*>(&Ch[r * QKV + cg]) =
                            *reinterpret_cast<uint32_t*>(&h);
                    } else {
                        float2 f = make_float2(fmaxf(v0, 0.0f), fmaxf(v1, 0.0f));
                        *reinterpret_cast<float2*>(&resf[r * VD + (cg - QKV)]) = f;
                    }
                }
                if (MODE == 1) {
                    __half2 h = __floats2half2_rn(fmaxf(v0, 0.0f), fmaxf(v1, 0.0f));
                    *reinterpret_cast<uint32_t*>(&Ch[r * Nn + cg]) =
                        *reinterpret_cast<uint32_t*>(&h);
                }
                if (MODE == 2) {
                    float2 rr = *reinterpret_cast<const float2*>(&resf[r * VD + cg]);
                    float2 f;
                    f.x = (rr.x + v0) * g_bnscale[cg]     + g_bnbias[cg];
                    f.y = (rr.y + v1) * g_bnscale[cg + 1] + g_bnbias[cg + 1];
                    *reinterpret_cast<float2*>(&Cf[r * Nn + cg]) = f;
                }
            }
        }
    }
}

// ---------------------------------------------------------------------------
// Tensor-core attention: one warp per voxel, 8 voxels per 256-thread block.
// (unchanged from round 8 — at DRAM floor)
// ---------------------------------------------------------------------------
#define VOX_B   3328          // 1280 (Q) + 1280 (K) + 768 (V)
#define SCALE_S 0.17677669529663687f

__global__ __launch_bounds__(256)
void attn_mma_kernel(const __half* __restrict__ qkvh, __half* __restrict__ outh)
{
    __shared__ __align__(16) char sm[8 * VOX_B];
    const uint32_t smemU = smem_u32(sm);

    const int tid  = threadIdx.x;
    const int wid  = tid >> 5;
    const int lane = tid & 31;
    const size_t vox0 = (size_t)blockIdx.x * 8;

    for (int i = tid; i < 1280; i += 256) {
        int slot = i / 160;
        int j = i - slot * 160;
        int off;
        if (j < 64)       off = (j >> 2) * 80 + (j & 3) * 16;
        else if (j < 128) off = 1280 + ((j - 64) >> 2) * 80 + ((j - 64) & 3) * 16;
        else              off = 2560 + ((j - 128) >> 1) * 48 + ((j - 128) & 1) * 16;
        cp16(smemU + slot * VOX_B + off, qkvh + (vox0 + slot) * QKV + j * 8);
    }
    cp_commit();
    cp_wait<0>();
    __syncthreads();

    const uint32_t qb = smemU + wid * VOX_B;
    const uint32_t kb = qb + 1280;
    const uint32_t vb = qb + 2560;
    const int g4 = lane >> 2;
    const int t4 = lane & 3;

    float sacc[2][4];
    #pragma unroll
    for (int nt = 0; nt < 2; nt++)
        #pragma unroll
        for (int r = 0; r < 4; r++) sacc[nt][r] = 0.0f;

    #pragma unroll
    for (int ks = 0; ks < 2; ks++) {
        uint32_t a[4];
        a[0] = lds32(qb + g4 * 80       + ks * 32 + t4 * 4);
        a[1] = lds32(qb + (g4 + 8) * 80 + ks * 32 + t4 * 4);
        a[2] = lds32(qb + g4 * 80       + ks * 32 + t4 * 4 + 16);
        a[3] = lds32(qb + (g4 + 8) * 80 + ks * 32 + t4 * 4 + 16);
        #pragma unroll
        for (int nt = 0; nt < 2; nt++) {
            uint32_t b0 = lds32(kb + (nt * 8 + g4) * 80 + ks * 32 + t4 * 4);
            uint32_t b1 = lds32(kb + (nt * 8 + g4) * 80 + ks * 32 + t4 * 4 + 16);
            mma16816(sacc[nt], a, b0, b1);
        }
    }

    uint32_t af[4];
    #pragma unroll
    for (int hf = 0; hf < 2; hf++) {
        float v00 = sacc[0][hf * 2]     * SCALE_S;
        float v01 = sacc[0][hf * 2 + 1] * SCALE_S;
        float v10 = sacc[1][hf * 2]     * SCALE_S;
        float v11 = sacc[1][hf * 2 + 1] * SCALE_S;
        float mx = fmaxf(fmaxf(v00, v01), fmaxf(v10, v11));
        mx = fmaxf(mx, __shfl_xor_sync(0xffffffffu, mx, 1));
        mx = fmaxf(mx, __shfl_xor_sync(0xffffffffu, mx, 2));
        float e00 = __expf(v00 - mx), e01 = __expf(v01 - mx);
        float e10 = __expf(v10 - mx), e11 = __expf(v11 - mx);
        float sum = e00 + e01 + e10 + e11;
        sum += __shfl_xor_sync(0xffffffffu, sum, 1);
        sum += __shfl_xor_sync(0xffffffffu, sum, 2);
        float inv = 1.0f / sum;
        __half2 p0 = __floats2half2_rn(e00 * inv, e01 * inv);
        __half2 p1 = __floats2half2_rn(e10 * inv, e11 * inv);
        af[hf]     = *reinterpret_cast<uint32_t*>(&p0);
        af[hf + 2] = *reinterpret_cast<uint32_t*>(&p1);
    }

    float oacc[2][4];
    #pragma unroll
    for (int nt = 0; nt < 2; nt++)
        #pragma unroll
        for (int r = 0; r < 4; r++) oacc[nt][r] = 0.0f;

    #pragma unroll
    for (int nt = 0; nt < 2; nt++) {
        uint32_t b[2];
        #pragma unroll
        for (int reg = 0; reg < 2; reg++) {
            int jr = 2 * t4 + reg * 8;
            uint32_t lo = lds16(vb + jr * 48       + (nt * 8 + g4) * 2);
            uint32_t hi = lds16(vb + (jr + 1) * 48 + (nt * 8 + g4) * 2);
            b[reg] = lo | (hi << 16);
        }
        mma16816(oacc[nt], af, b[0], b[1]);
    }

    __half* dst = outh + (vox0 + wid) * VD;
    #pragma unroll
    for (int nt = 0; nt < 2; nt++) {
        #pragma unroll
        for (int hf = 0; hf < 2; hf++) {
            __half2 h = __floats2half2_rn(oacc[nt][hf * 2], oacc[nt][hf * 2 + 1]);
            int r = g4 + 8 * hf;
            int c = nt * 8 + 2 * t4;
            *reinterpret_cast<uint32_t*>(&dst[r * DV + c]) =
                *reinterpret_cast<uint32_t*>(&h);
        }
    }
}

// ---------------------------------------------------------------------------
// Launch
// ---------------------------------------------------------------------------
extern "C" void kernel_launch(void* const* d_in, const int* in_sizes, int n_in,
                              void* d_out, int out_size)
{
    const float* x     = (const float*)d_in[0];
    const float* Wq    = (const float*)d_in[1];
    const float* bq    = (const float*)d_in[2];
    const float* Wk    = (const float*)d_in[3];
    const float* bk    = (const float*)d_in[4];
    const float* Wv    = (const float*)d_in[5];
    const float* bv    = (const float*)d_in[6];
    const float* W1    = (const float*)d_in[7];
    const float* b1    = (const float*)d_in[8];
    const float* Wo    = (const float*)d_in[9];
    const float* bo    = (const float*)d_in[10];
    const float* Wc    = (const float*)d_in[11];
    const float* bc    = (const float*)d_in[12];
    const float* gamma = (const float*)d_in[13];
    const float* beta  = (const float*)d_in[14];
    const float* mu    = (const float*)d_in[15];
    const float* var   = (const float*)d_in[16];
    float* out = (float*)d_out;

    void* p;
    cudaGetSymbolAddress(&p, g_WcatT);  __half* WcatT = (__half*)p;
    cudaGetSymbolAddress(&p, g_W1T);    __half* W1T   = (__half*)p;
    cudaGetSymbolAddress(&p, g_WoT);    __half* WoT   = (__half*)p;
    cudaGetSymbolAddress(&p, g_bcat);   float*  bcat  = (float*)p;
    cudaGetSymbolAddress(&p, g_xh);     __half* xh    = (__half*)p;
    cudaGetSymbolAddress(&p, g_qkvh);   __half* qkvh  = (__half*)p;
    cudaGetSymbolAddress(&p, g_res);    float*  resf  = (float*)p;
    cudaGetSymbolAddress(&p, g_attnh);  __half* attnh = (__half*)p;
    cudaGetSymbolAddress(&p, g_interh); __half* interh = (__half*)p;

    const int SMEM = NSTAGE * STAGE_BYTES;   // 98304
    cudaFuncSetAttribute(gemm_h<0>, cudaFuncAttributeMaxDynamicSharedMemorySize, SMEM);
    cudaFuncSetAttribute(gemm_h<1>, cudaFuncAttributeMaxDynamicSharedMemorySize, SMEM);
    cudaFuncSetAttribute(gemm_h<2>, cudaFuncAttributeMaxDynamicSharedMemorySize, SMEM);

    pack_kernel<<<512, 256>>>(Wq, bq, Wk, bk, Wv, bv, W1, Wo, Wc, bc,
                              gamma, beta, mu, var);
    x2h_kernel<<<4096, 256>>>((const float4*)x, (uint2*)xh);

    // qkv (fp16) + res (f32) = x @ Wcat + bcat
    {
        dim3 grid(CAT / 128, NVOX / 128);
        gemm_h<0><<<grid, 256, SMEM>>>(xh, WcatT, qkvh, resf, QKV, CIN, bcat);
    }

    attn_mma_kernel<<<NVOX / 8, 256>>>(qkvh, attnh);

    // inter = relu(attn @ W1 + b1) fp16
    {
        dim3 grid(FF / 128, NVOX / 128);
        gemm_h<1><<<grid, 256, SMEM>>>(attnh, W1T, interh, nullptr, FF, VD, b1);
    }

    // out = (res + inter @ Wo + bo) * bnscale + bnbias
    {
        dim3 grid(VD / 128, NVOX / 128);
        gemm_h<2><<<grid, 256, SMEM>>>(interh, WoT, out, resf, VD, FF, bo);
    }
}